// round 3
// baseline (speedup 1.0000x reference)
#include <cuda_runtime.h>
#include <cstdint>
#include <math.h>

#define NHEADS   16
#define NKV      4
#define HDIM     128
#define HIDDEN   2048
#define MAXSEQ   1024
#define EPSV     1e-6f
#define QSCALE   0.088388347648318447f   /* 1/sqrt(128) */
#define NSLICE   16                      /* K-split for GEMMs */
#define KSLICE   (HIDDEN / NSLICE)       /* 128 */
#define KC       32                      /* smem chunk */
#define NSPLIT   4                       /* attention seq split */

typedef unsigned long long ull;

// ---------------- scratch ---------------------------------------------------
__device__ __align__(16) float g_part[24 * NSLICE * 32 * 128]; // GEMM partials
__device__ __align__(16) float g_q[32 * NHEADS * HDIM];
__device__ __align__(16) float g_k[32 * NKV * HDIM];
__device__ __align__(16) float g_v[32 * NKV * HDIM];
__device__ __align__(16) float g_pa[32 * NKV * NSPLIT * 4 * HDIM]; // attn partials
__device__ float g_pm[32 * NKV * NSPLIT * 4];                      // partial max
__device__ float g_ps[32 * NKV * NSPLIT * 4];                      // partial sum

// packed dual-fp32 FMA (FFMA2) — PTX-only on sm_103a
__device__ __forceinline__ ull fma2(ull a, ull b, ull c) {
    ull d;
    asm("fma.rn.f32x2 %0, %1, %2, %3;" : "=l"(d) : "l"(a), "l"(b), "l"(c));
    return d;
}

// ---------------- GEMM shared-memory layout (dynamic, 66.8KB) --------------
struct GemmSmem {
    float2 x_s[KSLICE][32];     // [k][b], x duplicated in .x/.y   (32 KB)
    float  w_s[2][KC][130];     // double-buffered W chunk         (33.3 KB)
    float  cw[32][NSPLIT];      // combine weights (gemm_o only)
};

// ---------------------------------------------------------------------------
// GEMM core: out[32 b][128 f] partial over one 128-wide K slice already
// staged in S->x_s. Wt points at the slice's first k column. 128 threads;
// per-thread 4(m) x 8(n as 4 f32x2 pairs). One __syncthreads per chunk,
// W LDG double-buffered through registers.
// ---------------------------------------------------------------------------
__device__ __forceinline__ void gemm_core(GemmSmem* S,
                                          const float* __restrict__ Wt,
                                          float* __restrict__ outp)
{
    const int tid = threadIdx.x;
    const int tn2 = (tid & 15) * 2;
    const int tm4 = (tid >> 4) * 4;
    const int kq  = (tid & 7) * 4;
    const int f0  = tid >> 3;

    ull acc[4][4];
#pragma unroll
    for (int i = 0; i < 4; i++)
#pragma unroll
        for (int p = 0; p < 4; p++) acc[i][p] = 0ULL;

    float4 wreg[8];
#pragma unroll
    for (int r = 0; r < 8; r++)
        wreg[r] = *(const float4*)(Wt + (size_t)(f0 + r * 16) * HIDDEN + kq);

    int buf = 0;
    for (int kc = 0; kc < KSLICE; kc += KC) {
        // stage prefetched W chunk
#pragma unroll
        for (int r = 0; r < 8; r++) {
            const int f = f0 + r * 16;
            S->w_s[buf][kq + 0][f] = wreg[r].x;
            S->w_s[buf][kq + 1][f] = wreg[r].y;
            S->w_s[buf][kq + 2][f] = wreg[r].z;
            S->w_s[buf][kq + 3][f] = wreg[r].w;
        }
        __syncthreads();
        // prefetch next chunk (LDG in flight under the FMA block)
        if (kc + KC < KSLICE) {
#pragma unroll
            for (int r = 0; r < 8; r++)
                wreg[r] = *(const float4*)(Wt + (size_t)(f0 + r * 16) * HIDDEN
                                           + kc + KC + kq);
        }
#pragma unroll
        for (int k = 0; k < KC; k++) {
            const float2* xr = &S->x_s[kc + k][0];
            const ulonglong2 xa = *(const ulonglong2*)(xr + tm4);
            const ulonglong2 xb = *(const ulonglong2*)(xr + tm4 + 2);
            const ull w0 = *(const ull*)&S->w_s[buf][k][tn2];
            const ull w1 = *(const ull*)&S->w_s[buf][k][tn2 + 32];
            const ull w2 = *(const ull*)&S->w_s[buf][k][tn2 + 64];
            const ull w3 = *(const ull*)&S->w_s[buf][k][tn2 + 96];
            acc[0][0] = fma2(w0, xa.x, acc[0][0]);
            acc[0][1] = fma2(w1, xa.x, acc[0][1]);
            acc[0][2] = fma2(w2, xa.x, acc[0][2]);
            acc[0][3] = fma2(w3, xa.x, acc[0][3]);
            acc[1][0] = fma2(w0, xa.y, acc[1][0]);
            acc[1][1] = fma2(w1, xa.y, acc[1][1]);
            acc[1][2] = fma2(w2, xa.y, acc[1][2]);
            acc[1][3] = fma2(w3, xa.y, acc[1][3]);
            acc[2][0] = fma2(w0, xb.x, acc[2][0]);
            acc[2][1] = fma2(w1, xb.x, acc[2][1]);
            acc[2][2] = fma2(w2, xb.x, acc[2][2]);
            acc[2][3] = fma2(w3, xb.x, acc[2][3]);
            acc[3][0] = fma2(w0, xb.y, acc[3][0]);
            acc[3][1] = fma2(w1, xb.y, acc[3][1]);
            acc[3][2] = fma2(w2, xb.y, acc[3][2]);
            acc[3][3] = fma2(w3, xb.y, acc[3][3]);
        }
        buf ^= 1;
    }
#pragma unroll
    for (int i = 0; i < 4; i++)
#pragma unroll
        for (int p = 0; p < 4; p++)
            *(ull*)(outp + (size_t)(tm4 + i) * 128 + tn2 + p * 32) = acc[i][p];
}

// tiles 0..15 = wq heads, 16..19 = wk, 20..23 = wv. grid (24, NSLICE) x 128
__global__ __launch_bounds__(128) void gemm_qkv(const float* __restrict__ x,
                                                const float* __restrict__ wq,
                                                const float* __restrict__ wk,
                                                const float* __restrict__ wv)
{
    extern __shared__ char smem[];
    GemmSmem* S = (GemmSmem*)smem;
    const int tile = blockIdx.x, slice = blockIdx.y;
    const int kstart = slice * KSLICE;
    const int tid = threadIdx.x;

    // stage X slice (32 b x 128 k), duplicated for f32x2
    for (int i = tid; i < 1024; i += 128) {
        const int b = i >> 5, d4 = (i & 31) * 4;
        float4 v = *(const float4*)(x + (size_t)b * HIDDEN + kstart + d4);
        S->x_s[d4 + 0][b] = make_float2(v.x, v.x);
        S->x_s[d4 + 1][b] = make_float2(v.y, v.y);
        S->x_s[d4 + 2][b] = make_float2(v.z, v.z);
        S->x_s[d4 + 3][b] = make_float2(v.w, v.w);
    }

    const float* Wt;
    if (tile < 16)      Wt = wq + (size_t)tile * 128 * HIDDEN;
    else if (tile < 20) Wt = wk + (size_t)(tile - 16) * 128 * HIDDEN;
    else                Wt = wv + (size_t)(tile - 20) * 128 * HIDDEN;

    gemm_core(S, Wt + kstart,
              g_part + (size_t)(tile * NSLICE + slice) * 4096);
}

// Output projection with fused flash-decode combine. slice == head index.
// grid (16, NSLICE) x 128
__global__ __launch_bounds__(128) void gemm_o(const float* __restrict__ wo)
{
    extern __shared__ char smem[];
    GemmSmem* S = (GemmSmem*)smem;
    const int tile = blockIdx.x, slice = blockIdx.y;
    const int kv = slice >> 2, h = slice & 3;
    const int tid = threadIdx.x;

    // combine weights for this head: cw[b][c] = exp(pm-m)/den
    if (tid < 32) {
        const int b = tid;
        const int pb = ((b * NKV + kv) * NSPLIT) * 4 + h;
        float m = -1e30f;
#pragma unroll
        for (int c = 0; c < NSPLIT; c++) m = fmaxf(m, g_pm[pb + c * 4]);
        float wc[NSPLIT], den = 0.f;
#pragma unroll
        for (int c = 0; c < NSPLIT; c++) {
            wc[c] = __expf(g_pm[pb + c * 4] - m);
            den   = fmaf(g_ps[pb + c * 4], wc[c], den);
        }
        const float inv = 1.f / den;
#pragma unroll
        for (int c = 0; c < NSPLIT; c++) S->cw[b][c] = wc[c] * inv;
    }
    __syncthreads();

    // stage combined attention output as X slice (32 b x 128 d)
    for (int i = tid; i < 1024; i += 128) {
        const int b = i >> 5, d4 = (i & 31) * 4;
        float4 a = make_float4(0.f, 0.f, 0.f, 0.f);
#pragma unroll
        for (int c = 0; c < NSPLIT; c++) {
            const float4 v = *(const float4*)&g_pa[
                (size_t)(((b * NKV + kv) * NSPLIT + c) * 4 + h) * HDIM + d4];
            const float w = S->cw[b][c];
            a.x = fmaf(w, v.x, a.x);
            a.y = fmaf(w, v.y, a.y);
            a.z = fmaf(w, v.z, a.z);
            a.w = fmaf(w, v.w, a.w);
        }
        S->x_s[d4 + 0][b] = make_float2(a.x, a.x);
        S->x_s[d4 + 1][b] = make_float2(a.y, a.y);
        S->x_s[d4 + 2][b] = make_float2(a.z, a.z);
        S->x_s[d4 + 3][b] = make_float2(a.w, a.w);
    }

    gemm_core(S, wo + (size_t)tile * 128 * HIDDEN + slice * KSLICE,
              g_part + (size_t)(tile * NSLICE + slice) * 4096);
}

// ---------------------------------------------------------------------------
// Reduce K-split partials, then RMSnorm + RoPE for q/k heads.
// grid (24, 32) x 128
// ---------------------------------------------------------------------------
__global__ __launch_bounds__(128) void reduce_norm_rope(
    const float* __restrict__ position,
    const float* __restrict__ qnw, const float* __restrict__ knw)
{
    const int head = blockIdx.x, b = blockIdx.y, d = threadIdx.x;
    const size_t base = (size_t)head * NSLICE * 4096 + (size_t)b * 128 + d;
    float v = 0.f;
#pragma unroll
    for (int s = 0; s < NSLICE; s++) v += g_part[base + (size_t)s * 4096];

    if (head >= 20) {
        g_v[(b * NKV + head - 20) * HDIM + d] = v;
        return;
    }

    __shared__ float red[4];
    __shared__ float sv[128];

    float sq = v * v;
#pragma unroll
    for (int off = 16; off; off >>= 1)
        sq += __shfl_xor_sync(0xffffffffu, sq, off);
    if ((d & 31) == 0) red[d >> 5] = sq;
    __syncthreads();
    const float ssq  = red[0] + red[1] + red[2] + red[3];
    const float norm = rsqrtf(ssq * (1.f / 128.f) + EPSV);
    const float nv   = v * norm * ((head < 16) ? qnw[d] : knw[d]);
    sv[d] = nv;
    __syncthreads();

    const float pos = position[0];
    const int   j   = d & 63;
    const float fr  = pos * exp2f((float)j * (-19.93156856932417f / 64.f));
    float c, s;
    sincosf(fr, &s, &c);
    const float other = (d < 64) ? sv[d + 64] : sv[d - 64];
    const float out   = (d < 64) ? (nv * c - other * s)
                                 : (nv * c + other * s);
    if (head < 16) g_q[(b * NHEADS + head) * HDIM + d] = out * QSCALE;
    else           g_k[(b * NKV + head - 16) * HDIM + d] = out;
}

// ---------------------------------------------------------------------------
// Attention partial: block (kv, b, split c). 4 q-heads share K/V reads.
// ---------------------------------------------------------------------------
__global__ __launch_bounds__(256) void attn_part(
    const float* __restrict__ k_cache, const float* __restrict__ v_cache,
    const float* __restrict__ position)
{
    const int kv = blockIdx.x, b = blockIdx.y, c = blockIdx.z;
    const int tid = threadIdx.x;
    const int lane = tid & 31, w = tid >> 5;
    const int pos = (int)position[0];
    const int S   = pos + 1;
    const int LEN = (S + NSPLIT - 1) / NSPLIT;
    const int lo  = c * LEN;
    const int hi  = min(S, lo + LEN);

    __shared__ float q_s[4][HDIM];
    __shared__ float sc[4][(MAXSEQ + NSPLIT - 1) / NSPLIT + 4];
    __shared__ float wred[8][4];
    __shared__ float gm[4];
    __shared__ float wout[8][4][HDIM];

    for (int i = tid; i < 4 * HDIM; i += 256) {
        const int h = i >> 7, d = i & 127;
        q_s[h][d] = g_q[(b * NHEADS + kv * 4 + h) * HDIM + d];
    }
    __syncthreads();

    float qr[4][4];
#pragma unroll
    for (int h = 0; h < 4; h++)
#pragma unroll
        for (int j = 0; j < 4; j++) qr[h][j] = q_s[h][lane * 4 + j];

    const float* kbase = k_cache + (size_t)(b * NKV + kv) * MAXSEQ * HDIM;
    const float* knew  = g_k + (b * NKV + kv) * HDIM;

    float wmax[4] = {-1e30f, -1e30f, -1e30f, -1e30f};

    for (int s0 = lo + w * 4; s0 < hi; s0 += 32) {
        float4 r[4];
#pragma unroll
        for (int u = 0; u < 4; u++) {
            const int s = s0 + u;
            if (s < hi) {
                const float* row = (s == pos) ? knew
                                              : (kbase + (size_t)s * HDIM);
                r[u] = *(const float4*)(row + lane * 4);
            }
        }
#pragma unroll
        for (int u = 0; u < 4; u++) {
            const int s = s0 + u;
            if (s < hi) {
                float d0 = fmaf(r[u].x, qr[0][0], fmaf(r[u].y, qr[0][1],
                           fmaf(r[u].z, qr[0][2], r[u].w * qr[0][3])));
                float d1 = fmaf(r[u].x, qr[1][0], fmaf(r[u].y, qr[1][1],
                           fmaf(r[u].z, qr[1][2], r[u].w * qr[1][3])));
                float d2 = fmaf(r[u].x, qr[2][0], fmaf(r[u].y, qr[2][1],
                           fmaf(r[u].z, qr[2][2], r[u].w * qr[2][3])));
                float d3 = fmaf(r[u].x, qr[3][0], fmaf(r[u].y, qr[3][1],
                           fmaf(r[u].z, qr[3][2], r[u].w * qr[3][3])));
#pragma unroll
                for (int off = 16; off; off >>= 1) {
                    d0 += __shfl_xor_sync(0xffffffffu, d0, off);
                    d1 += __shfl_xor_sync(0xffffffffu, d1, off);
                    d2 += __shfl_xor_sync(0xffffffffu, d2, off);
                    d3 += __shfl_xor_sync(0xffffffffu, d3, off);
                }
                wmax[0] = fmaxf(wmax[0], d0);
                wmax[1] = fmaxf(wmax[1], d1);
                wmax[2] = fmaxf(wmax[2], d2);
                wmax[3] = fmaxf(wmax[3], d3);
                if (lane == 0) {
                    sc[0][s - lo] = d0; sc[1][s - lo] = d1;
                    sc[2][s - lo] = d2; sc[3][s - lo] = d3;
                }
            }
        }
    }
    if (lane == 0) {
        wred[w][0] = wmax[0]; wred[w][1] = wmax[1];
        wred[w][2] = wmax[2]; wred[w][3] = wmax[3];
    }
    __syncthreads();
    if (tid < 4) {
        float m = wred[0][tid];
#pragma unroll
        for (int i = 1; i < 8; i++) m = fmaxf(m, wred[i][tid]);
        gm[tid] = m;
    }
    __syncthreads();

    float lsum[4] = {0.f, 0.f, 0.f, 0.f};
#pragma unroll
    for (int h = 0; h < 4; h++) {
        const float m = gm[h];
        for (int s = lo + tid; s < hi; s += 256) {
            const float e = __expf(sc[h][s - lo] - m);
            sc[h][s - lo] = e;
            lsum[h] += e;
        }
    }
#pragma unroll
    for (int h = 0; h < 4; h++) {
        float v = lsum[h];
#pragma unroll
        for (int off = 16; off; off >>= 1)
            v += __shfl_xor_sync(0xffffffffu, v, off);
        if (lane == 0) wred[w][h] = v;
    }
    __syncthreads();
    if (tid < 4) {
        float v = 0.f;
#pragma unroll
        for (int i = 0; i < 8; i++) v += wred[i][tid];
        const int pbase = ((b * NKV + kv) * NSPLIT + c) * 4 + tid;
        g_ps[pbase] = v;
        g_pm[pbase] = gm[tid];
    }
    __syncthreads();

    const float* vbase = v_cache + (size_t)(b * NKV + kv) * MAXSEQ * HDIM;
    const float* vnew  = g_v + (b * NKV + kv) * HDIM;
    float acc[4][4];
#pragma unroll
    for (int h = 0; h < 4; h++)
#pragma unroll
        for (int j = 0; j < 4; j++) acc[h][j] = 0.f;

    for (int s0 = lo + w * 4; s0 < hi; s0 += 32) {
        float4 r[4];
#pragma unroll
        for (int u = 0; u < 4; u++) {
            const int s = s0 + u;
            if (s < hi) {
                const float* row = (s == pos) ? vnew
                                              : (vbase + (size_t)s * HDIM);
                r[u] = *(const float4*)(row + lane * 4);
            }
        }
#pragma unroll
        for (int u = 0; u < 4; u++) {
            const int s = s0 + u;
            if (s < hi) {
                const float p0 = sc[0][s - lo], p1 = sc[1][s - lo];
                const float p2 = sc[2][s - lo], p3 = sc[3][s - lo];
                acc[0][0] = fmaf(p0, r[u].x, acc[0][0]);
                acc[0][1] = fmaf(p0, r[u].y, acc[0][1]);
                acc[0][2] = fmaf(p0, r[u].z, acc[0][2]);
                acc[0][3] = fmaf(p0, r[u].w, acc[0][3]);
                acc[1][0] = fmaf(p1, r[u].x, acc[1][0]);
                acc[1][1] = fmaf(p1, r[u].y, acc[1][1]);
                acc[1][2] = fmaf(p1, r[u].z, acc[1][2]);
                acc[1][3] = fmaf(p1, r[u].w, acc[1][3]);
                acc[2][0] = fmaf(p2, r[u].x, acc[2][0]);
                acc[2][1] = fmaf(p2, r[u].y, acc[2][1]);
                acc[2][2] = fmaf(p2, r[u].z, acc[2][2]);
                acc[2][3] = fmaf(p2, r[u].w, acc[2][3]);
                acc[3][0] = fmaf(p3, r[u].x, acc[3][0]);
                acc[3][1] = fmaf(p3, r[u].y, acc[3][1]);
                acc[3][2] = fmaf(p3, r[u].z, acc[3][2]);
                acc[3][3] = fmaf(p3, r[u].w, acc[3][3]);
            }
        }
    }
#pragma unroll
    for (int h = 0; h < 4; h++)
#pragma unroll
        for (int j = 0; j < 4; j++)
            wout[w][h][lane * 4 + j] = acc[h][j];
    __syncthreads();

    for (int i = tid; i < 4 * HDIM; i += 256) {
        const int h = i >> 7, d = i & 127;
        float v = 0.f;
#pragma unroll
        for (int ww = 0; ww < 8; ww++) v += wout[ww][h][d];
        g_pa[(((size_t)(b * NKV + kv) * NSPLIT + c) * 4 + h) * HDIM + d] = v;
    }
}

// Final K-split reduce for output projection. grid (16, 32) x 128
__global__ __launch_bounds__(128) void reduce_out(float* __restrict__ out)
{
    const int tile = blockIdx.x, b = blockIdx.y, d = threadIdx.x;
    const size_t base = (size_t)tile * NSLICE * 4096 + (size_t)b * 128 + d;
    float v = 0.f;
#pragma unroll
    for (int s = 0; s < NSLICE; s++) v += g_part[base + (size_t)s * 4096];
    out[b * HIDDEN + tile * 128 + d] = v;
}

// ---------------------------------------------------------------------------
extern "C" void kernel_launch(void* const* d_in, const int* in_sizes, int n_in,
                              void* d_out, int out_size)
{
    const float* x        = (const float*)d_in[0];
    const float* position = (const float*)d_in[1];
    const float* k_cache  = (const float*)d_in[3];
    const float* v_cache  = (const float*)d_in[4];
    const float* wq       = (const float*)d_in[6];
    const float* wk       = (const float*)d_in[7];
    const float* wv       = (const float*)d_in[8];
    const float* wo       = (const float*)d_in[9];
    const float* qnw      = (const float*)d_in[10];
    const float* knw      = (const float*)d_in[11];
    float* out            = (float*)d_out;

    const int smem = (int)sizeof(GemmSmem);
    cudaFuncSetAttribute(gemm_qkv, cudaFuncAttributeMaxDynamicSharedMemorySize, smem);
    cudaFuncSetAttribute(gemm_o,   cudaFuncAttributeMaxDynamicSharedMemorySize, smem);

    gemm_qkv<<<dim3(24, NSLICE), 128, smem>>>(x, wq, wk, wv);
    reduce_norm_rope<<<dim3(24, 32), 128>>>(position, qnw, knw);
    attn_part<<<dim3(NKV, 32, NSPLIT), 256>>>(k_cache, v_cache, position);
    gemm_o<<<dim3(16, NSLICE), 128, smem>>>(wo);
    reduce_out<<<dim3(16, 32), 128>>>(out);
}

// round 4
// speedup vs baseline: 1.0005x; 1.0005x over previous
#include <cuda_runtime.h>
#include <cstdint>
#include <math.h>

#define NHEADS   16
#define NKV      4
#define HDIM     128
#define HIDDEN   2048
#define MAXSEQ   1024
#define EPSV     1e-6f
#define QSCALE   0.088388347648318447f   /* 1/sqrt(128) */
#define NSLICE   16                      /* K-split for GEMMs */
#define KSLICE   (HIDDEN / NSLICE)       /* 128 */
#define KTEAM    (KSLICE / 2)            /* 64 k per team */
#define KC       16                      /* smem W chunk */
#define NSPLIT   8                       /* attention seq split */

typedef unsigned long long ull;

// ---------------- scratch ---------------------------------------------------
__device__ __align__(16) float g_part[24 * NSLICE * 32 * 128];
__device__ __align__(16) float g_q[32 * NHEADS * HDIM];
__device__ __align__(16) float g_k[32 * NKV * HDIM];
__device__ __align__(16) float g_v[32 * NKV * HDIM];
__device__ __align__(16) float g_pa[32 * NKV * NSPLIT * 4 * HDIM];
__device__ float g_pm[32 * NKV * NSPLIT * 4];
__device__ float g_ps[32 * NKV * NSPLIT * 4];

// packed dual-fp32 FMA (FFMA2) — PTX-only on sm_103a
__device__ __forceinline__ ull fma2(ull a, ull b, ull c) {
    ull d;
    asm("fma.rn.f32x2 %0, %1, %2, %3;" : "=l"(d) : "l"(a), "l"(b), "l"(c));
    return d;
}
__device__ __forceinline__ ull addp(ull a, ull b) {
    float2 fa = *(float2*)&a, fb = *(float2*)&b;
    fa.x += fb.x; fa.y += fb.y;
    return *(ull*)&fa;
}

// ---------------- GEMM shared memory (~102 KB dynamic) ----------------------
struct GemmSmem {
    float2 x_s[KSLICE][34];        // [k][b] duplicated; pad 34 => 16B align
    float  w_s[2][2][KC][130];     // [team][buf][k][f]
    float  cw[32][NSPLIT];         // combine weights (gemm_o)
};

// ---------------------------------------------------------------------------
// GEMM core: 256 threads = 2 k-teams x (4 m-groups x 32 n-cols).
// Thread tile m8 x n4 (pairs at nc*2 and nc*2+64). X slice pre-staged in
// S->x_s (duplicated float2). Wt points at this slice's first k column.
// ---------------------------------------------------------------------------
__device__ __forceinline__ void gemm_core(GemmSmem* S,
                                          const float* __restrict__ Wt,
                                          float* __restrict__ outp)
{
    const int tid  = threadIdx.x;
    const int team = tid >> 7;
    const int wtid = tid & 127;
    const int mg   = wtid >> 5;          // m base = mg*8
    const int nc   = wtid & 31;          // n pairs nc*2, nc*2+64

    const int kq = (wtid & 3) * 4;       // W loader: k quad
    const int f0 = wtid >> 2;            // W loader: f base (+32p)

    const float* Wteam = Wt + team * KTEAM;

    ull acc[8][2];
#pragma unroll
    for (int i = 0; i < 8; i++) { acc[i][0] = 0ULL; acc[i][1] = 0ULL; }

    float4 wreg[4];
#pragma unroll
    for (int p = 0; p < 4; p++)
        wreg[p] = *(const float4*)(Wteam + (size_t)(f0 + p * 32) * HIDDEN + kq);

    int buf = 0;
#pragma unroll 1
    for (int c = 0; c < KTEAM / KC; c++) {
#pragma unroll
        for (int p = 0; p < 4; p++) {
            const int f = f0 + p * 32;
            S->w_s[team][buf][kq + 0][f] = wreg[p].x;
            S->w_s[team][buf][kq + 1][f] = wreg[p].y;
            S->w_s[team][buf][kq + 2][f] = wreg[p].z;
            S->w_s[team][buf][kq + 3][f] = wreg[p].w;
        }
        __syncthreads();
        if (c + 1 < KTEAM / KC) {
#pragma unroll
            for (int p = 0; p < 4; p++)
                wreg[p] = *(const float4*)(Wteam + (size_t)(f0 + p * 32) * HIDDEN
                                           + (c + 1) * KC + kq);
        }
        const int kbase = team * KTEAM + c * KC;
#pragma unroll
        for (int k = 0; k < KC; k++) {
            const float2* xr = &S->x_s[kbase + k][mg * 8];
            const ulonglong2 x0 = *(const ulonglong2*)(xr + 0);
            const ulonglong2 x1 = *(const ulonglong2*)(xr + 2);
            const ulonglong2 x2 = *(const ulonglong2*)(xr + 4);
            const ulonglong2 x3 = *(const ulonglong2*)(xr + 6);
            const ull w0 = *(const ull*)&S->w_s[team][buf][k][nc * 2];
            const ull w1 = *(const ull*)&S->w_s[team][buf][k][nc * 2 + 64];
            acc[0][0] = fma2(w0, x0.x, acc[0][0]);
            acc[0][1] = fma2(w1, x0.x, acc[0][1]);
            acc[1][0] = fma2(w0, x0.y, acc[1][0]);
            acc[1][1] = fma2(w1, x0.y, acc[1][1]);
            acc[2][0] = fma2(w0, x1.x, acc[2][0]);
            acc[2][1] = fma2(w1, x1.x, acc[2][1]);
            acc[3][0] = fma2(w0, x1.y, acc[3][0]);
            acc[3][1] = fma2(w1, x1.y, acc[3][1]);
            acc[4][0] = fma2(w0, x2.x, acc[4][0]);
            acc[4][1] = fma2(w1, x2.x, acc[4][1]);
            acc[5][0] = fma2(w0, x2.y, acc[5][0]);
            acc[5][1] = fma2(w1, x2.y, acc[5][1]);
            acc[6][0] = fma2(w0, x3.x, acc[6][0]);
            acc[6][1] = fma2(w1, x3.x, acc[6][1]);
            acc[7][0] = fma2(w0, x3.y, acc[7][0]);
            acc[7][1] = fma2(w1, x3.y, acc[7][1]);
        }
        buf ^= 1;
        __syncthreads();
    }

    // combine k-teams through smem (reuse x_s region; both teams are past it)
    ull* A = (ull*)&S->x_s[0][0];        // [m][64 pairs]
    if (team == 1) {
#pragma unroll
        for (int mi = 0; mi < 8; mi++) {
            A[(mg * 8 + mi) * 64 + nc]      = acc[mi][0];
            A[(mg * 8 + mi) * 64 + nc + 32] = acc[mi][1];
        }
    }
    __syncthreads();
    if (team == 0) {
#pragma unroll
        for (int mi = 0; mi < 8; mi++) {
            const int m = mg * 8 + mi;
            const ull s0 = addp(acc[mi][0], A[m * 64 + nc]);
            const ull s1 = addp(acc[mi][1], A[m * 64 + nc + 32]);
            *(ull*)(outp + (size_t)m * 128 + nc * 2)      = s0;
            *(ull*)(outp + (size_t)m * 128 + nc * 2 + 64) = s1;
        }
    }
}

// stage X slice (32 b x 128 k) into x_s, duplicated float2
__device__ __forceinline__ void stage_x(GemmSmem* S, const float* __restrict__ x,
                                        int kstart)
{
    for (int i = threadIdx.x; i < 1024; i += 256) {
        const int b = i >> 5, d4 = (i & 31) * 4;
        float4 v = *(const float4*)(x + (size_t)b * HIDDEN + kstart + d4);
        S->x_s[d4 + 0][b] = make_float2(v.x, v.x);
        S->x_s[d4 + 1][b] = make_float2(v.y, v.y);
        S->x_s[d4 + 2][b] = make_float2(v.z, v.z);
        S->x_s[d4 + 3][b] = make_float2(v.w, v.w);
    }
}

// tiles 0..15 = wq heads, 16..19 = wk, 20..23 = wv. grid (24, NSLICE) x 256
__global__ __launch_bounds__(256, 2) void gemm_qkv(const float* __restrict__ x,
                                                   const float* __restrict__ wq,
                                                   const float* __restrict__ wk,
                                                   const float* __restrict__ wv)
{
    extern __shared__ char smem[];
    GemmSmem* S = (GemmSmem*)smem;
    const int tile = blockIdx.x, slice = blockIdx.y;
    const int kstart = slice * KSLICE;

    stage_x(S, x, kstart);

    const float* Wt;
    if (tile < 16)      Wt = wq + (size_t)tile * 128 * HIDDEN;
    else if (tile < 20) Wt = wk + (size_t)(tile - 16) * 128 * HIDDEN;
    else                Wt = wv + (size_t)(tile - 20) * 128 * HIDDEN;

    gemm_core(S, Wt + kstart, g_part + (size_t)(tile * NSLICE + slice) * 4096);
}

// Output projection with fused flash-decode combine. slice == head index.
// grid (16, NSLICE) x 256
__global__ __launch_bounds__(256, 2) void gemm_o(const float* __restrict__ wo)
{
    extern __shared__ char smem[];
    GemmSmem* S = (GemmSmem*)smem;
    const int tile = blockIdx.x, slice = blockIdx.y;
    const int kv = slice >> 2, h = slice & 3;
    const int tid = threadIdx.x;

    if (tid < 32) {
        const int b = tid;
        const int pb = ((b * NKV + kv) * NSPLIT) * 4 + h;
        float m = -1e30f;
#pragma unroll
        for (int c = 0; c < NSPLIT; c++) m = fmaxf(m, g_pm[pb + c * 4]);
        float wc[NSPLIT], den = 0.f;
#pragma unroll
        for (int c = 0; c < NSPLIT; c++) {
            wc[c] = __expf(g_pm[pb + c * 4] - m);
            den   = fmaf(g_ps[pb + c * 4], wc[c], den);
        }
        const float inv = 1.f / den;
#pragma unroll
        for (int c = 0; c < NSPLIT; c++) S->cw[b][c] = wc[c] * inv;
    }
    __syncthreads();

    for (int i = tid; i < 1024; i += 256) {
        const int b = i >> 5, d4 = (i & 31) * 4;
        float4 a = make_float4(0.f, 0.f, 0.f, 0.f);
#pragma unroll
        for (int c = 0; c < NSPLIT; c++) {
            const float4 v = *(const float4*)&g_pa[
                (size_t)(((b * NKV + kv) * NSPLIT + c) * 4 + h) * HDIM + d4];
            const float w = S->cw[b][c];
            a.x = fmaf(w, v.x, a.x);
            a.y = fmaf(w, v.y, a.y);
            a.z = fmaf(w, v.z, a.z);
            a.w = fmaf(w, v.w, a.w);
        }
        S->x_s[d4 + 0][b] = make_float2(a.x, a.x);
        S->x_s[d4 + 1][b] = make_float2(a.y, a.y);
        S->x_s[d4 + 2][b] = make_float2(a.z, a.z);
        S->x_s[d4 + 3][b] = make_float2(a.w, a.w);
    }

    gemm_core(S, wo + (size_t)tile * 128 * HIDDEN + slice * KSLICE,
              g_part + (size_t)(tile * NSLICE + slice) * 4096);
}

// ---------------------------------------------------------------------------
// Reduce K-split partials, then RMSnorm + RoPE. grid (24, 32) x 128
// ---------------------------------------------------------------------------
__global__ __launch_bounds__(128) void reduce_norm_rope(
    const float* __restrict__ position,
    const float* __restrict__ qnw, const float* __restrict__ knw)
{
    const int head = blockIdx.x, b = blockIdx.y, d = threadIdx.x;
    const size_t base = (size_t)head * NSLICE * 4096 + (size_t)b * 128 + d;
    float v = 0.f;
#pragma unroll
    for (int s = 0; s < NSLICE; s++) v += g_part[base + (size_t)s * 4096];

    if (head >= 20) {
        g_v[(b * NKV + head - 20) * HDIM + d] = v;
        return;
    }

    __shared__ float red[4];
    __shared__ float sv[128];

    float sq = v * v;
#pragma unroll
    for (int off = 16; off; off >>= 1)
        sq += __shfl_xor_sync(0xffffffffu, sq, off);
    if ((d & 31) == 0) red[d >> 5] = sq;
    __syncthreads();
    const float ssq  = red[0] + red[1] + red[2] + red[3];
    const float norm = rsqrtf(ssq * (1.f / 128.f) + EPSV);
    const float nv   = v * norm * ((head < 16) ? qnw[d] : knw[d]);
    sv[d] = nv;
    __syncthreads();

    const float pos = position[0];
    const int   j   = d & 63;
    const float fr  = pos * exp2f((float)j * (-19.93156856932417f / 64.f));
    float c, s;
    sincosf(fr, &s, &c);
    const float other = (d < 64) ? sv[d + 64] : sv[d - 64];
    const float out   = (d < 64) ? (nv * c - other * s)
                                 : (nv * c + other * s);
    if (head < 16) g_q[(b * NHEADS + head) * HDIM + d] = out * QSCALE;
    else           g_k[(b * NKV + head - 16) * HDIM + d] = out;
}

// ---------------------------------------------------------------------------
// Attention partial: block (kv, b, split c). 4 q-heads share K/V reads.
// ---------------------------------------------------------------------------
__global__ __launch_bounds__(256) void attn_part(
    const float* __restrict__ k_cache, const float* __restrict__ v_cache,
    const float* __restrict__ position)
{
    const int kv = blockIdx.x, b = blockIdx.y, c = blockIdx.z;
    const int tid = threadIdx.x;
    const int lane = tid & 31, w = tid >> 5;
    const int pos = (int)position[0];
    const int S   = pos + 1;
    const int LEN = (S + NSPLIT - 1) / NSPLIT;
    const int lo  = c * LEN;
    const int hi  = min(S, lo + LEN);

    __shared__ float q_s[4][HDIM];
    __shared__ float sc[4][(MAXSEQ + NSPLIT - 1) / NSPLIT + 4];
    __shared__ float wred[8][4];
    __shared__ float gm[4];
    __shared__ float wout[8][4][HDIM];

    for (int i = tid; i < 4 * HDIM; i += 256) {
        const int h = i >> 7, d = i & 127;
        q_s[h][d] = g_q[(b * NHEADS + kv * 4 + h) * HDIM + d];
    }
    __syncthreads();

    float qr[4][4];
#pragma unroll
    for (int h = 0; h < 4; h++)
#pragma unroll
        for (int j = 0; j < 4; j++) qr[h][j] = q_s[h][lane * 4 + j];

    const float* kbase = k_cache + (size_t)(b * NKV + kv) * MAXSEQ * HDIM;
    const float* knew  = g_k + (b * NKV + kv) * HDIM;

    float wmax[4] = {-1e30f, -1e30f, -1e30f, -1e30f};

    for (int s0 = lo + w * 4; s0 < hi; s0 += 32) {
        float4 r[4];
#pragma unroll
        for (int u = 0; u < 4; u++) {
            const int s = s0 + u;
            if (s < hi) {
                const float* row = (s == pos) ? knew
                                              : (kbase + (size_t)s * HDIM);
                r[u] = *(const float4*)(row + lane * 4);
            }
        }
#pragma unroll
        for (int u = 0; u < 4; u++) {
            const int s = s0 + u;
            if (s < hi) {
                float d0 = fmaf(r[u].x, qr[0][0], fmaf(r[u].y, qr[0][1],
                           fmaf(r[u].z, qr[0][2], r[u].w * qr[0][3])));
                float d1 = fmaf(r[u].x, qr[1][0], fmaf(r[u].y, qr[1][1],
                           fmaf(r[u].z, qr[1][2], r[u].w * qr[1][3])));
                float d2 = fmaf(r[u].x, qr[2][0], fmaf(r[u].y, qr[2][1],
                           fmaf(r[u].z, qr[2][2], r[u].w * qr[2][3])));
                float d3 = fmaf(r[u].x, qr[3][0], fmaf(r[u].y, qr[3][1],
                           fmaf(r[u].z, qr[3][2], r[u].w * qr[3][3])));
#pragma unroll
                for (int off = 16; off; off >>= 1) {
                    d0 += __shfl_xor_sync(0xffffffffu, d0, off);
                    d1 += __shfl_xor_sync(0xffffffffu, d1, off);
                    d2 += __shfl_xor_sync(0xffffffffu, d2, off);
                    d3 += __shfl_xor_sync(0xffffffffu, d3, off);
                }
                wmax[0] = fmaxf(wmax[0], d0);
                wmax[1] = fmaxf(wmax[1], d1);
                wmax[2] = fmaxf(wmax[2], d2);
                wmax[3] = fmaxf(wmax[3], d3);
                if (lane == 0) {
                    sc[0][s - lo] = d0; sc[1][s - lo] = d1;
                    sc[2][s - lo] = d2; sc[3][s - lo] = d3;
                }
            }
        }
    }
    if (lane == 0) {
        wred[w][0] = wmax[0]; wred[w][1] = wmax[1];
        wred[w][2] = wmax[2]; wred[w][3] = wmax[3];
    }
    __syncthreads();
    if (tid < 4) {
        float m = wred[0][tid];
#pragma unroll
        for (int i = 1; i < 8; i++) m = fmaxf(m, wred[i][tid]);
        gm[tid] = m;
    }
    __syncthreads();

    float lsum[4] = {0.f, 0.f, 0.f, 0.f};
#pragma unroll
    for (int h = 0; h < 4; h++) {
        const float m = gm[h];
        for (int s = lo + tid; s < hi; s += 256) {
            const float e = __expf(sc[h][s - lo] - m);
            sc[h][s - lo] = e;
            lsum[h] += e;
        }
    }
#pragma unroll
    for (int h = 0; h < 4; h++) {
        float v = lsum[h];
#pragma unroll
        for (int off = 16; off; off >>= 1)
            v += __shfl_xor_sync(0xffffffffu, v, off);
        if (lane == 0) wred[w][h] = v;
    }
    __syncthreads();
    if (tid < 4) {
        float v = 0.f;
#pragma unroll
        for (int i = 0; i < 8; i++) v += wred[i][tid];
        const int pbase = ((b * NKV + kv) * NSPLIT + c) * 4 + tid;
        g_ps[pbase] = v;
        g_pm[pbase] = gm[tid];
    }
    __syncthreads();

    const float* vbase = v_cache + (size_t)(b * NKV + kv) * MAXSEQ * HDIM;
    const float* vnew  = g_v + (b * NKV + kv) * HDIM;
    float acc[4][4];
#pragma unroll
    for (int h = 0; h < 4; h++)
#pragma unroll
        for (int j = 0; j < 4; j++) acc[h][j] = 0.f;

    for (int s0 = lo + w * 4; s0 < hi; s0 += 32) {
        float4 r[4];
#pragma unroll
        for (int u = 0; u < 4; u++) {
            const int s = s0 + u;
            if (s < hi) {
                const float* row = (s == pos) ? vnew
                                              : (vbase + (size_t)s * HDIM);
                r[u] = *(const float4*)(row + lane * 4);
            }
        }
#pragma unroll
        for (int u = 0; u < 4; u++) {
            const int s = s0 + u;
            if (s < hi) {
                const float p0 = sc[0][s - lo], p1 = sc[1][s - lo];
                const float p2 = sc[2][s - lo], p3 = sc[3][s - lo];
                acc[0][0] = fmaf(p0, r[u].x, acc[0][0]);
                acc[0][1] = fmaf(p0, r[u].y, acc[0][1]);
                acc[0][2] = fmaf(p0, r[u].z, acc[0][2]);
                acc[0][3] = fmaf(p0, r[u].w, acc[0][3]);
                acc[1][0] = fmaf(p1, r[u].x, acc[1][0]);
                acc[1][1] = fmaf(p1, r[u].y, acc[1][1]);
                acc[1][2] = fmaf(p1, r[u].z, acc[1][2]);
                acc[1][3] = fmaf(p1, r[u].w, acc[1][3]);
                acc[2][0] = fmaf(p2, r[u].x, acc[2][0]);
                acc[2][1] = fmaf(p2, r[u].y, acc[2][1]);
                acc[2][2] = fmaf(p2, r[u].z, acc[2][2]);
                acc[2][3] = fmaf(p2, r[u].w, acc[2][3]);
                acc[3][0] = fmaf(p3, r[u].x, acc[3][0]);
                acc[3][1] = fmaf(p3, r[u].y, acc[3][1]);
                acc[3][2] = fmaf(p3, r[u].z, acc[3][2]);
                acc[3][3] = fmaf(p3, r[u].w, acc[3][3]);
            }
        }
    }
#pragma unroll
    for (int h = 0; h < 4; h++)
#pragma unroll
        for (int j = 0; j < 4; j++)
            wout[w][h][lane * 4 + j] = acc[h][j];
    __syncthreads();

    for (int i = tid; i < 4 * HDIM; i += 256) {
        const int h = i >> 7, d = i & 127;
        float v = 0.f;
#pragma unroll
        for (int ww = 0; ww < 8; ww++) v += wout[ww][h][d];
        g_pa[(((size_t)(b * NKV + kv) * NSPLIT + c) * 4 + h) * HDIM + d] = v;
    }
}

// Final K-split reduce for output projection. grid (16, 32) x 128
__global__ __launch_bounds__(128) void reduce_out(float* __restrict__ out)
{
    const int tile = blockIdx.x, b = blockIdx.y, d = threadIdx.x;
    const size_t base = (size_t)tile * NSLICE * 4096 + (size_t)b * 128 + d;
    float v = 0.f;
#pragma unroll
    for (int s = 0; s < NSLICE; s++) v += g_part[base + (size_t)s * 4096];
    out[b * HIDDEN + tile * 128 + d] = v;
}

// ---------------------------------------------------------------------------
extern "C" void kernel_launch(void* const* d_in, const int* in_sizes, int n_in,
                              void* d_out, int out_size)
{
    const float* x        = (const float*)d_in[0];
    const float* position = (const float*)d_in[1];
    const float* k_cache  = (const float*)d_in[3];
    const float* v_cache  = (const float*)d_in[4];
    const float* wq       = (const float*)d_in[6];
    const float* wk       = (const float*)d_in[7];
    const float* wv       = (const float*)d_in[8];
    const float* wo       = (const float*)d_in[9];
    const float* qnw      = (const float*)d_in[10];
    const float* knw      = (const float*)d_in[11];
    float* out            = (float*)d_out;

    const int smem = (int)sizeof(GemmSmem);
    cudaFuncSetAttribute(gemm_qkv, cudaFuncAttributeMaxDynamicSharedMemorySize, smem);
    cudaFuncSetAttribute(gemm_o,   cudaFuncAttributeMaxDynamicSharedMemorySize, smem);

    gemm_qkv<<<dim3(24, NSLICE), 256, smem>>>(x, wq, wk, wv);
    reduce_norm_rope<<<dim3(24, 32), 128>>>(position, qnw, knw);
    attn_part<<<dim3(NKV, 32, NSPLIT), 256>>>(k_cache, v_cache, position);
    gemm_o<<<dim3(16, NSLICE), 256, smem>>>(wo);
    reduce_out<<<dim3(16, 32), 128>>>(out);
}

// round 6
// speedup vs baseline: 1.1710x; 1.1705x over previous
#include <cuda_runtime.h>
#include <cuda_bf16.h>
#include <cstdint>
#include <math.h>

#define NHEADS   16
#define NKV      4
#define HDIM     128
#define HIDDEN   2048
#define MAXSEQ   1024
#define EPSV     1e-6f
#define QSCALE   0.088388347648318447f   /* 1/sqrt(128) */
#define NSPLIT   8                       /* attention seq split */
#define KS       8                       /* GEMM k-split */
#define KCH      32                      /* k per staged chunk */
#define NCH      ((HIDDEN / KS) / KCH)   /* 8 chunks per block */

// smem layout (dynamic, 51200 B): A[2buf][2hl][32][80B], B[2buf][2hl][128][80B]
#define A_HL   2560                      /* 32*80 */
#define A_BUF  5120
#define B_OFF  10240
#define B_HL   10240                     /* 128*80 */
#define B_BUF  20480
#define SMEM_MMA 51200

// ---------------- scratch ---------------------------------------------------
__device__ __align__(16) float g_part[24 * KS * 32 * 128];
__device__ __align__(16) __nv_bfloat16 g_xh[32 * HIDDEN];
__device__ __align__(16) __nv_bfloat16 g_xl[32 * HIDDEN];
__device__ __align__(16) __nv_bfloat16 g_ah[32 * HIDDEN];
__device__ __align__(16) __nv_bfloat16 g_al[32 * HIDDEN];
__device__ __align__(16) float g_q[32 * NHEADS * HDIM];
__device__ __align__(16) float g_k[32 * NKV * HDIM];
__device__ __align__(16) float g_v[32 * NKV * HDIM];
__device__ __align__(16) float g_pa[32 * NKV * NSPLIT * 4 * HDIM];
__device__ float g_pm[32 * NKV * NSPLIT * 4];
__device__ float g_ps[32 * NKV * NSPLIT * 4];

// ---------------- wrappers ---------------------------------------------------
__device__ __forceinline__ uint32_t smem_u32(const void* p) {
    uint32_t a;
    asm("{ .reg .u64 t; cvta.to.shared.u64 t, %1; cvt.u32.u64 %0, t; }"
        : "=r"(a) : "l"(p));
    return a;
}
__device__ __forceinline__ void ldsm4(uint32_t& r0, uint32_t& r1,
                                      uint32_t& r2, uint32_t& r3, uint32_t a) {
    asm volatile("ldmatrix.sync.aligned.m8n8.x4.shared.b16 {%0,%1,%2,%3}, [%4];"
                 : "=r"(r0), "=r"(r1), "=r"(r2), "=r"(r3) : "r"(a));
}
__device__ __forceinline__ void mma16816(float* c,
                                         uint32_t a0, uint32_t a1, uint32_t a2,
                                         uint32_t a3, uint32_t b0, uint32_t b1) {
    asm volatile(
        "mma.sync.aligned.m16n8k16.row.col.f32.bf16.bf16.f32 "
        "{%0,%1,%2,%3}, {%4,%5,%6,%7}, {%8,%9}, {%0,%1,%2,%3};"
        : "+f"(c[0]), "+f"(c[1]), "+f"(c[2]), "+f"(c[3])
        : "r"(a0), "r"(a1), "r"(a2), "r"(a3), "r"(b0), "r"(b1));
}
__device__ __forceinline__ uint32_t bpack(__nv_bfloat16 a, __nv_bfloat16 b) {
    __nv_bfloat162 t = __halves2bfloat162(a, b);
    return *(uint32_t*)&t;
}

// ---------------- GEMM staging ----------------------------------------------
struct WRegs {
    float4 v[4];     // 16 fp32 of W (one 128x32 chunk / 256 threads)
    uint2  ah, al;   // 4+4 bf16 of A
};

__device__ __forceinline__ void ldg_chunk(WRegs& r,
    const __nv_bfloat16* __restrict__ ah, const __nv_bfloat16* __restrict__ al,
    const float* __restrict__ W, int k0)
{
    const int tid  = threadIdx.x;
    const int arow = tid >> 3, akq = (tid & 7) * 4;
    r.ah = *(const uint2*)(ah + (size_t)arow * HIDDEN + k0 + akq);
    r.al = *(const uint2*)(al + (size_t)arow * HIDDEN + k0 + akq);
    const int brow = tid >> 1, bk = (tid & 1) * 16;
#pragma unroll
    for (int j = 0; j < 4; j++)
        r.v[j] = *(const float4*)(W + (size_t)brow * HIDDEN + k0 + bk + j * 4);
}

__device__ __forceinline__ void sts_chunk(uint8_t* smem, int buf, const WRegs& r)
{
    const int tid  = threadIdx.x;
    const int arow = tid >> 3, akq = (tid & 7) * 4;
    uint8_t* A = smem + buf * A_BUF;
    *(uint2*)(A + arow * 80 + akq * 2)        = r.ah;
    *(uint2*)(A + A_HL + arow * 80 + akq * 2) = r.al;

    const int brow = tid >> 1, bk = (tid & 1) * 16;
    uint8_t* Bh = smem + B_OFF + buf * B_BUF;
    uint8_t* Bl = Bh + B_HL;
    uint32_t h[8], l[8];
#pragma unroll
    for (int j = 0; j < 4; j++) {
        const float4 v = r.v[j];
        const __nv_bfloat16 h0 = __float2bfloat16(v.x);
        const __nv_bfloat16 h1 = __float2bfloat16(v.y);
        const __nv_bfloat16 h2 = __float2bfloat16(v.z);
        const __nv_bfloat16 h3 = __float2bfloat16(v.w);
        h[j * 2 + 0] = bpack(h0, h1);
        h[j * 2 + 1] = bpack(h2, h3);
        l[j * 2 + 0] = bpack(__float2bfloat16(v.x - __bfloat162float(h0)),
                             __float2bfloat16(v.y - __bfloat162float(h1)));
        l[j * 2 + 1] = bpack(__float2bfloat16(v.z - __bfloat162float(h2)),
                             __float2bfloat16(v.w - __bfloat162float(h3)));
    }
    *(uint4*)(Bh + brow * 80 + bk * 2)      = make_uint4(h[0], h[1], h[2], h[3]);
    *(uint4*)(Bh + brow * 80 + bk * 2 + 16) = make_uint4(h[4], h[5], h[6], h[7]);
    *(uint4*)(Bl + brow * 80 + bk * 2)      = make_uint4(l[0], l[1], l[2], l[3]);
    *(uint4*)(Bl + brow * 80 + bk * 2 + 16) = make_uint4(l[4], l[5], l[6], l[7]);
}

// ---------------------------------------------------------------------------
// mma GEMM body: C[32 m][128 n] partial over (HIDDEN/KS) k starting at k0.
// 8 warps: warp w owns n in [w*16, w*16+16). bf16 hi/lo 3-term split.
// ---------------------------------------------------------------------------
__device__ __forceinline__ void gemm_mma_body(
    const __nv_bfloat16* __restrict__ ah, const __nv_bfloat16* __restrict__ al,
    const float* __restrict__ W, float* __restrict__ outp, int k0)
{
    extern __shared__ uint8_t smem[];
    const uint32_t sb = smem_u32(smem);
    const int tid = threadIdx.x, warp = tid >> 5, lane = tid & 31;
    const int j = lane >> 3, r8 = lane & 7;

    float acc[2][2][4];
#pragma unroll
    for (int a = 0; a < 2; a++)
#pragma unroll
        for (int b = 0; b < 2; b++)
#pragma unroll
            for (int q = 0; q < 4; q++) acc[a][b][q] = 0.f;

    WRegs r;
    ldg_chunk(r, ah, al, W, k0);
    sts_chunk(smem, 0, r);
    __syncthreads();

#pragma unroll 1
    for (int c = 0; c < NCH; c++) {
        if (c + 1 < NCH) ldg_chunk(r, ah, al, W, k0 + (c + 1) * KCH);

        const uint32_t Ab = sb + (c & 1) * A_BUF;
        const uint32_t Bb = sb + B_OFF + (c & 1) * B_BUF;
#pragma unroll
        for (int ks = 0; ks < 2; ks++) {
            const uint32_t aaddr = Ab
                + (uint32_t)(((j & 1) * 8 + r8) * 80 + (ks * 2 + (j >> 1)) * 16);
            const uint32_t baddr = Bb
                + (uint32_t)((warp * 16 + (j >> 1) * 8 + r8) * 80
                             + (ks * 2 + (j & 1)) * 16);
            uint32_t f0, f1, f2, f3, g0, g1, g2, g3;
            uint32_t p0, p1, p2, p3, q0, q1, q2, q3;
            uint32_t bh0, bh1, bh2, bh3, bl0, bl1, bl2, bl3;
            ldsm4(f0, f1, f2, f3, aaddr);                    // Ah m0-15
            ldsm4(g0, g1, g2, g3, aaddr + 16 * 80);          // Ah m16-31
            ldsm4(p0, p1, p2, p3, aaddr + A_HL);             // Al m0-15
            ldsm4(q0, q1, q2, q3, aaddr + A_HL + 16 * 80);   // Al m16-31
            ldsm4(bh0, bh1, bh2, bh3, baddr);                // Bh n16 x k16
            ldsm4(bl0, bl1, bl2, bl3, baddr + B_HL);         // Bl

            mma16816(acc[0][0], f0, f1, f2, f3, bh0, bh1);
            mma16816(acc[0][1], f0, f1, f2, f3, bh2, bh3);
            mma16816(acc[1][0], g0, g1, g2, g3, bh0, bh1);
            mma16816(acc[1][1], g0, g1, g2, g3, bh2, bh3);
            mma16816(acc[0][0], f0, f1, f2, f3, bl0, bl1);
            mma16816(acc[0][1], f0, f1, f2, f3, bl2, bl3);
            mma16816(acc[1][0], g0, g1, g2, g3, bl0, bl1);
            mma16816(acc[1][1], g0, g1, g2, g3, bl2, bl3);
            mma16816(acc[0][0], p0, p1, p2, p3, bh0, bh1);
            mma16816(acc[0][1], p0, p1, p2, p3, bh2, bh3);
            mma16816(acc[1][0], q0, q1, q2, q3, bh0, bh1);
            mma16816(acc[1][1], q0, q1, q2, q3, bh2, bh3);
        }
        if (c + 1 < NCH) sts_chunk(smem, (c + 1) & 1, r);
        __syncthreads();
    }

#pragma unroll
    for (int mt = 0; mt < 2; mt++)
#pragma unroll
        for (int nh = 0; nh < 2; nh++) {
            const float* cc = acc[mt][nh];
            const int m0 = mt * 16 + (lane >> 2);
            const int n  = warp * 16 + nh * 8 + (lane & 3) * 2;
            *(float2*)(outp + (size_t)m0 * 128 + n)       = make_float2(cc[0], cc[1]);
            *(float2*)(outp + (size_t)(m0 + 8) * 128 + n) = make_float2(cc[2], cc[3]);
        }
}

// QKV: grid (24, KS) x 256. tiles 0-15 wq, 16-19 wk, 20-23 wv.
__global__ __launch_bounds__(256, 2) void gemm_qkv_mma(
    const float* __restrict__ wq, const float* __restrict__ wk,
    const float* __restrict__ wv)
{
    const int tile = blockIdx.x, slice = blockIdx.y;
    const float* W;
    if (tile < 16)      W = wq + (size_t)tile * 128 * HIDDEN;
    else if (tile < 20) W = wk + (size_t)(tile - 16) * 128 * HIDDEN;
    else                W = wv + (size_t)(tile - 20) * 128 * HIDDEN;
    gemm_mma_body(g_xh, g_xl, W,
                  g_part + (size_t)(tile * KS + slice) * 4096,
                  slice * (HIDDEN / KS));
}

// O-proj: grid (16, KS) x 256.
__global__ __launch_bounds__(256, 2) void gemm_o_mma(const float* __restrict__ wo)
{
    const int tile = blockIdx.x, slice = blockIdx.y;
    gemm_mma_body(g_ah, g_al, wo + (size_t)tile * 128 * HIDDEN,
                  g_part + (size_t)(tile * KS + slice) * 4096,
                  slice * (HIDDEN / KS));
}

// ---------------------------------------------------------------------------
// x fp32 -> bf16 hi/lo. grid 32 x 256.
// ---------------------------------------------------------------------------
__global__ __launch_bounds__(256) void prep_x(const float* __restrict__ x)
{
    const int b = blockIdx.x;
    const int c0 = threadIdx.x * 8;
    const float* xr = x + (size_t)b * HIDDEN + c0;
    uint32_t hp[4], lp[4];
#pragma unroll
    for (int g = 0; g < 2; g++) {
        const float4 v = *(const float4*)(xr + g * 4);
        const __nv_bfloat16 h0 = __float2bfloat16(v.x);
        const __nv_bfloat16 h1 = __float2bfloat16(v.y);
        const __nv_bfloat16 h2 = __float2bfloat16(v.z);
        const __nv_bfloat16 h3 = __float2bfloat16(v.w);
        hp[g * 2 + 0] = bpack(h0, h1);
        hp[g * 2 + 1] = bpack(h2, h3);
        lp[g * 2 + 0] = bpack(__float2bfloat16(v.x - __bfloat162float(h0)),
                              __float2bfloat16(v.y - __bfloat162float(h1)));
        lp[g * 2 + 1] = bpack(__float2bfloat16(v.z - __bfloat162float(h2)),
                              __float2bfloat16(v.w - __bfloat162float(h3)));
    }
    *(uint4*)(g_xh + (size_t)b * HIDDEN + c0) = make_uint4(hp[0], hp[1], hp[2], hp[3]);
    *(uint4*)(g_xl + (size_t)b * HIDDEN + c0) = make_uint4(lp[0], lp[1], lp[2], lp[3]);
}

// ---------------------------------------------------------------------------
// Reduce QKV partials (KS), RMSnorm + RoPE. grid (24, 32) x 128.
// ---------------------------------------------------------------------------
__global__ __launch_bounds__(128) void reduce_norm_rope(
    const float* __restrict__ position,
    const float* __restrict__ qnw, const float* __restrict__ knw)
{
    const int head = blockIdx.x, b = blockIdx.y, d = threadIdx.x;
    const size_t base = (size_t)head * KS * 4096 + (size_t)b * 128 + d;
    float v = 0.f;
#pragma unroll
    for (int s = 0; s < KS; s++) v += g_part[base + (size_t)s * 4096];

    if (head >= 20) {
        g_v[(b * NKV + head - 20) * HDIM + d] = v;
        return;
    }

    __shared__ float red[4];
    __shared__ float sv[128];

    float sq = v * v;
#pragma unroll
    for (int off = 16; off; off >>= 1)
        sq += __shfl_xor_sync(0xffffffffu, sq, off);
    if ((d & 31) == 0) red[d >> 5] = sq;
    __syncthreads();
    const float ssq  = red[0] + red[1] + red[2] + red[3];
    const float norm = rsqrtf(ssq * (1.f / 128.f) + EPSV);
    const float nv   = v * norm * ((head < 16) ? qnw[d] : knw[d]);
    sv[d] = nv;
    __syncthreads();

    const float pos = position[0];
    const int   jj  = d & 63;
    const float fr  = pos * exp2f((float)jj * (-19.93156856932417f / 64.f));
    float c, s;
    sincosf(fr, &s, &c);
    const float other = (d < 64) ? sv[d + 64] : sv[d - 64];
    const float out   = (d < 64) ? (nv * c - other * s)
                                 : (nv * c + other * s);
    if (head < 16) g_q[(b * NHEADS + head) * HDIM + d] = out * QSCALE;
    else           g_k[(b * NKV + head - 16) * HDIM + d] = out;
}

// ---------------------------------------------------------------------------
// Attention partial: block (kv, b, split c). 4 q-heads share K/V reads.
// ---------------------------------------------------------------------------
__global__ __launch_bounds__(256) void attn_part(
    const float* __restrict__ k_cache, const float* __restrict__ v_cache,
    const float* __restrict__ position)
{
    const int kv = blockIdx.x, b = blockIdx.y, c = blockIdx.z;
    const int tid = threadIdx.x;
    const int lane = tid & 31, w = tid >> 5;
    const int pos = (int)position[0];
    const int S   = pos + 1;
    const int LEN = (S + NSPLIT - 1) / NSPLIT;
    const int lo  = c * LEN;
    const int hi  = min(S, lo + LEN);

    __shared__ float q_s[4][HDIM];
    __shared__ float sc[4][(MAXSEQ + NSPLIT - 1) / NSPLIT + 4];
    __shared__ float wred[8][4];
    __shared__ float gm[4];
    __shared__ float wout[8][4][HDIM];

    for (int i = tid; i < 4 * HDIM; i += 256) {
        const int h = i >> 7, d = i & 127;
        q_s[h][d] = g_q[(b * NHEADS + kv * 4 + h) * HDIM + d];
    }
    __syncthreads();

    float qr[4][4];
#pragma unroll
    for (int h = 0; h < 4; h++)
#pragma unroll
        for (int jj = 0; jj < 4; jj++) qr[h][jj] = q_s[h][lane * 4 + jj];

    const float* kbase = k_cache + (size_t)(b * NKV + kv) * MAXSEQ * HDIM;
    const float* knew  = g_k + (b * NKV + kv) * HDIM;

    float wmax[4] = {-1e30f, -1e30f, -1e30f, -1e30f};

    for (int s0 = lo + w * 4; s0 < hi; s0 += 32) {
        float4 r[4];
#pragma unroll
        for (int u = 0; u < 4; u++) {
            const int s = s0 + u;
            if (s < hi) {
                const float* row = (s == pos) ? knew
                                              : (kbase + (size_t)s * HDIM);
                r[u] = *(const float4*)(row + lane * 4);
            }
        }
#pragma unroll
        for (int u = 0; u < 4; u++) {
            const int s = s0 + u;
            if (s < hi) {
                float d0 = fmaf(r[u].x, qr[0][0], fmaf(r[u].y, qr[0][1],
                           fmaf(r[u].z, qr[0][2], r[u].w * qr[0][3])));
                float d1 = fmaf(r[u].x, qr[1][0], fmaf(r[u].y, qr[1][1],
                           fmaf(r[u].z, qr[1][2], r[u].w * qr[1][3])));
                float d2 = fmaf(r[u].x, qr[2][0], fmaf(r[u].y, qr[2][1],
                           fmaf(r[u].z, qr[2][2], r[u].w * qr[2][3])));
                float d3 = fmaf(r[u].x, qr[3][0], fmaf(r[u].y, qr[3][1],
                           fmaf(r[u].z, qr[3][2], r[u].w * qr[3][3])));
#pragma unroll
                for (int off = 16; off; off >>= 1) {
                    d0 += __shfl_xor_sync(0xffffffffu, d0, off);
                    d1 += __shfl_xor_sync(0xffffffffu, d1, off);
                    d2 += __shfl_xor_sync(0xffffffffu, d2, off);
                    d3 += __shfl_xor_sync(0xffffffffu, d3, off);
                }
                wmax[0] = fmaxf(wmax[0], d0);
                wmax[1] = fmaxf(wmax[1], d1);
                wmax[2] = fmaxf(wmax[2], d2);
                wmax[3] = fmaxf(wmax[3], d3);
                if (lane == 0) {
                    sc[0][s - lo] = d0; sc[1][s - lo] = d1;
                    sc[2][s - lo] = d2; sc[3][s - lo] = d3;
                }
            }
        }
    }
    if (lane == 0) {
        wred[w][0] = wmax[0]; wred[w][1] = wmax[1];
        wred[w][2] = wmax[2]; wred[w][3] = wmax[3];
    }
    __syncthreads();
    if (tid < 4) {
        float m = wred[0][tid];
#pragma unroll
        for (int i = 1; i < 8; i++) m = fmaxf(m, wred[i][tid]);
        gm[tid] = m;
    }
    __syncthreads();

    float lsum[4] = {0.f, 0.f, 0.f, 0.f};
#pragma unroll
    for (int h = 0; h < 4; h++) {
        const float m = gm[h];
        for (int s = lo + tid; s < hi; s += 256) {
            const float e = __expf(sc[h][s - lo] - m);
            sc[h][s - lo] = e;
            lsum[h] += e;
        }
    }
#pragma unroll
    for (int h = 0; h < 4; h++) {
        float v = lsum[h];
#pragma unroll
        for (int off = 16; off; off >>= 1)
            v += __shfl_xor_sync(0xffffffffu, v, off);
        if (lane == 0) wred[w][h] = v;
    }
    __syncthreads();
    if (tid < 4) {
        float v = 0.f;
#pragma unroll
        for (int i = 0; i < 8; i++) v += wred[i][tid];
        const int pbase = ((b * NKV + kv) * NSPLIT + c) * 4 + tid;
        g_ps[pbase] = v;
        g_pm[pbase] = gm[tid];
    }
    __syncthreads();

    const float* vbase = v_cache + (size_t)(b * NKV + kv) * MAXSEQ * HDIM;
    const float* vnew  = g_v + (b * NKV + kv) * HDIM;
    float acc[4][4];
#pragma unroll
    for (int h = 0; h < 4; h++)
#pragma unroll
        for (int jj = 0; jj < 4; jj++) acc[h][jj] = 0.f;

    for (int s0 = lo + w * 4; s0 < hi; s0 += 32) {
        float4 r[4];
#pragma unroll
        for (int u = 0; u < 4; u++) {
            const int s = s0 + u;
            if (s < hi) {
                const float* row = (s == pos) ? vnew
                                              : (vbase + (size_t)s * HDIM);
                r[u] = *(const float4*)(row + lane * 4);
            }
        }
#pragma unroll
        for (int u = 0; u < 4; u++) {
            const int s = s0 + u;
            if (s < hi) {
                const float p0 = sc[0][s - lo], p1 = sc[1][s - lo];
                const float p2 = sc[2][s - lo], p3 = sc[3][s - lo];
                acc[0][0] = fmaf(p0, r[u].x, acc[0][0]);
                acc[0][1] = fmaf(p0, r[u].y, acc[0][1]);
                acc[0][2] = fmaf(p0, r[u].z, acc[0][2]);
                acc[0][3] = fmaf(p0, r[u].w, acc[0][3]);
                acc[1][0] = fmaf(p1, r[u].x, acc[1][0]);
                acc[1][1] = fmaf(p1, r[u].y, acc[1][1]);
                acc[1][2] = fmaf(p1, r[u].z, acc[1][2]);
                acc[1][3] = fmaf(p1, r[u].w, acc[1][3]);
                acc[2][0] = fmaf(p2, r[u].x, acc[2][0]);
                acc[2][1] = fmaf(p2, r[u].y, acc[2][1]);
                acc[2][2] = fmaf(p2, r[u].z, acc[2][2]);
                acc[2][3] = fmaf(p2, r[u].w, acc[2][3]);
                acc[3][0] = fmaf(p3, r[u].x, acc[3][0]);
                acc[3][1] = fmaf(p3, r[u].y, acc[3][1]);
                acc[3][2] = fmaf(p3, r[u].z, acc[3][2]);
                acc[3][3] = fmaf(p3, r[u].w, acc[3][3]);
            }
        }
    }
#pragma unroll
    for (int h = 0; h < 4; h++)
#pragma unroll
        for (int jj = 0; jj < 4; jj++)
            wout[w][h][lane * 4 + jj] = acc[h][jj];
    __syncthreads();

    for (int i = tid; i < 4 * HDIM; i += 256) {
        const int h = i >> 7, d = i & 127;
        float v = 0.f;
#pragma unroll
        for (int ww = 0; ww < 8; ww++) v += wout[ww][h][d];
        g_pa[(((size_t)(b * NKV + kv) * NSPLIT + c) * 4 + h) * HDIM + d] = v;
    }
}

// ---------------------------------------------------------------------------
// Combine flash partials, write attention output as bf16 hi/lo.
// grid (16 heads, 32 b) x 128.
// ---------------------------------------------------------------------------
__global__ __launch_bounds__(128) void combine_conv()
{
    const int hidx = blockIdx.x, b = blockIdx.y, d = threadIdx.x;
    const int kv = hidx >> 2, h = hidx & 3;
    const int pb = ((b * NKV + kv) * NSPLIT) * 4 + h;

    float m = -1e30f;
#pragma unroll
    for (int c = 0; c < NSPLIT; c++) m = fmaxf(m, g_pm[pb + c * 4]);
    float den = 0.f, wc[NSPLIT];
#pragma unroll
    for (int c = 0; c < NSPLIT; c++) {
        wc[c] = __expf(g_pm[pb + c * 4] - m);
        den   = fmaf(g_ps[pb + c * 4], wc[c], den);
    }
    const float inv = 1.f / den;

    float val = 0.f;
#pragma unroll
    for (int c = 0; c < NSPLIT; c++)
        val = fmaf(wc[c],
                   g_pa[(size_t)(((b * NKV + kv) * NSPLIT + c) * 4 + h) * HDIM + d],
                   val);
    const float r = val * inv;
    const __nv_bfloat16 hv = __float2bfloat16(r);
    const __nv_bfloat16 lv = __float2bfloat16(r - __bfloat162float(hv));
    g_ah[(size_t)b * HIDDEN + hidx * 128 + d] = hv;
    g_al[(size_t)b * HIDDEN + hidx * 128 + d] = lv;
}

// Final reduce for O projection. grid (16, 32) x 128.
__global__ __launch_bounds__(128) void reduce_out(float* __restrict__ out)
{
    const int tile = blockIdx.x, b = blockIdx.y, d = threadIdx.x;
    const size_t base = (size_t)tile * KS * 4096 + (size_t)b * 128 + d;
    float v = 0.f;
#pragma unroll
    for (int s = 0; s < KS; s++) v += g_part[base + (size_t)s * 4096];
    out[b * HIDDEN + tile * 128 + d] = v;
}

// ---------------------------------------------------------------------------
extern "C" void kernel_launch(void* const* d_in, const int* in_sizes, int n_in,
                              void* d_out, int out_size)
{
    const float* x        = (const float*)d_in[0];
    const float* position = (const float*)d_in[1];
    const float* k_cache  = (const float*)d_in[3];
    const float* v_cache  = (const float*)d_in[4];
    const float* wq       = (const float*)d_in[6];
    const float* wk       = (const float*)d_in[7];
    const float* wv       = (const float*)d_in[8];
    const float* wo       = (const float*)d_in[9];
    const float* qnw      = (const float*)d_in[10];
    const float* knw      = (const float*)d_in[11];
    float* out            = (float*)d_out;

    cudaFuncSetAttribute(gemm_qkv_mma, cudaFuncAttributeMaxDynamicSharedMemorySize, SMEM_MMA);
    cudaFuncSetAttribute(gemm_o_mma,   cudaFuncAttributeMaxDynamicSharedMemorySize, SMEM_MMA);

    prep_x<<<32, 256>>>(x);
    gemm_qkv_mma<<<dim3(24, KS), 256, SMEM_MMA>>>(wq, wk, wv);
    reduce_norm_rope<<<dim3(24, 32), 128>>>(position, qnw, knw);
    attn_part<<<dim3(NKV, 32, NSPLIT), 256>>>(k_cache, v_cache, position);
    combine_conv<<<dim3(16, 32), 128>>>();
    gemm_o_mma<<<dim3(16, KS), 256, SMEM_MMA>>>(wo);
    reduce_out<<<dim3(16, 32), 128>>>(out);
}

// round 7
// speedup vs baseline: 1.2206x; 1.0423x over previous
#include <cuda_runtime.h>
#include <cuda_bf16.h>
#include <cstdint>
#include <math.h>

#define NHEADS   16
#define NKV      4
#define HDIM     128
#define HIDDEN   2048
#define MAXSEQ   1024
#define EPSV     1e-6f
#define QSCALE   0.088388347648318447f   /* 1/sqrt(128) */
#define NSPLIT   8                       /* attention seq split */
#define KS       8                       /* GEMM k-split */
#define KCH      32                      /* k per staged chunk */
#define NCH      ((HIDDEN / KS) / KCH)   /* 8 chunks per block */

// smem layout (dynamic, 51200 B): A[2buf][2hl][32][80B], B[2buf][2hl][128][80B]
#define A_HL   2560
#define A_BUF  5120
#define B_OFF  10240
#define B_HL   10240
#define B_BUF  20480
#define SMEM_MMA 51200

// ---------------- scratch ---------------------------------------------------
__device__ __align__(16) float g_part[24 * KS * 32 * 128];
__device__ __align__(16) __nv_bfloat16 g_xh[32 * HIDDEN];
__device__ __align__(16) __nv_bfloat16 g_xl[32 * HIDDEN];
__device__ __align__(16) __nv_bfloat16 g_ah[32 * HIDDEN];
__device__ __align__(16) __nv_bfloat16 g_al[32 * HIDDEN];
__device__ __align__(16) float g_q[32 * NHEADS * HDIM];
__device__ __align__(16) float g_k[32 * NKV * HDIM];
__device__ __align__(16) float g_v[32 * NKV * HDIM];
__device__ __align__(16) float g_pa[32 * NKV * NSPLIT * 4 * HDIM];
__device__ float g_pm[32 * NKV * NSPLIT * 4];
__device__ float g_ps[32 * NKV * NSPLIT * 4];

// ---------------- wrappers ---------------------------------------------------
__device__ __forceinline__ uint32_t smem_u32(const void* p) {
    uint32_t a;
    asm("{ .reg .u64 t; cvta.to.shared.u64 t, %1; cvt.u32.u64 %0, t; }"
        : "=r"(a) : "l"(p));
    return a;
}
__device__ __forceinline__ void ldsm4(uint32_t& r0, uint32_t& r1,
                                      uint32_t& r2, uint32_t& r3, uint32_t a) {
    asm volatile("ldmatrix.sync.aligned.m8n8.x4.shared.b16 {%0,%1,%2,%3}, [%4];"
                 : "=r"(r0), "=r"(r1), "=r"(r2), "=r"(r3) : "r"(a));
}
__device__ __forceinline__ void mma16816(float* c,
                                         uint32_t a0, uint32_t a1, uint32_t a2,
                                         uint32_t a3, uint32_t b0, uint32_t b1) {
    asm volatile(
        "mma.sync.aligned.m16n8k16.row.col.f32.bf16.bf16.f32 "
        "{%0,%1,%2,%3}, {%4,%5,%6,%7}, {%8,%9}, {%0,%1,%2,%3};"
        : "+f"(c[0]), "+f"(c[1]), "+f"(c[2]), "+f"(c[3])
        : "r"(a0), "r"(a1), "r"(a2), "r"(a3), "r"(b0), "r"(b1));
}
__device__ __forceinline__ uint32_t bpack(__nv_bfloat16 a, __nv_bfloat16 b) {
    __nv_bfloat162 t = __halves2bfloat162(a, b);
    return *(uint32_t*)&t;
}

// 4-head packed butterfly: returns full 128-dim dot for head (lane&3),
// given per-lane 4-dim partials v0..v3 for heads 0..3. 6 shuffles.
__device__ __forceinline__ float reduce4(float v0, float v1, float v2, float v3,
                                         int lane)
{
    const bool b0 = lane & 1, b1 = lane & 2;
    float x = b0 ? v1 : v0;
    float y = b0 ? v0 : v1;
    x += __shfl_xor_sync(0xffffffffu, y, 1);
    float z = b0 ? v3 : v2;
    float u = b0 ? v2 : v3;
    z += __shfl_xor_sync(0xffffffffu, u, 1);
    float p = b1 ? z : x;
    float q = b1 ? x : z;
    p += __shfl_xor_sync(0xffffffffu, q, 2);
    p += __shfl_xor_sync(0xffffffffu, p, 4);
    p += __shfl_xor_sync(0xffffffffu, p, 8);
    p += __shfl_xor_sync(0xffffffffu, p, 16);
    return p;   // lane l: dot for head l&3
}

// ---------------- GEMM staging (unchanged from round 6) ---------------------
struct WRegs {
    float4 v[4];
    uint2  ah, al;
};

__device__ __forceinline__ void ldg_chunk(WRegs& r,
    const __nv_bfloat16* __restrict__ ah, const __nv_bfloat16* __restrict__ al,
    const float* __restrict__ W, int k0)
{
    const int tid  = threadIdx.x;
    const int arow = tid >> 3, akq = (tid & 7) * 4;
    r.ah = *(const uint2*)(ah + (size_t)arow * HIDDEN + k0 + akq);
    r.al = *(const uint2*)(al + (size_t)arow * HIDDEN + k0 + akq);
    const int brow = tid >> 1, bk = (tid & 1) * 16;
#pragma unroll
    for (int j = 0; j < 4; j++)
        r.v[j] = *(const float4*)(W + (size_t)brow * HIDDEN + k0 + bk + j * 4);
}

__device__ __forceinline__ void sts_chunk(uint8_t* smem, int buf, const WRegs& r)
{
    const int tid  = threadIdx.x;
    const int arow = tid >> 3, akq = (tid & 7) * 4;
    uint8_t* A = smem + buf * A_BUF;
    *(uint2*)(A + arow * 80 + akq * 2)        = r.ah;
    *(uint2*)(A + A_HL + arow * 80 + akq * 2) = r.al;

    const int brow = tid >> 1, bk = (tid & 1) * 16;
    uint8_t* Bh = smem + B_OFF + buf * B_BUF;
    uint8_t* Bl = Bh + B_HL;
    uint32_t h[8], l[8];
#pragma unroll
    for (int j = 0; j < 4; j++) {
        const float4 v = r.v[j];
        const __nv_bfloat16 h0 = __float2bfloat16(v.x);
        const __nv_bfloat16 h1 = __float2bfloat16(v.y);
        const __nv_bfloat16 h2 = __float2bfloat16(v.z);
        const __nv_bfloat16 h3 = __float2bfloat16(v.w);
        h[j * 2 + 0] = bpack(h0, h1);
        h[j * 2 + 1] = bpack(h2, h3);
        l[j * 2 + 0] = bpack(__float2bfloat16(v.x - __bfloat162float(h0)),
                             __float2bfloat16(v.y - __bfloat162float(h1)));
        l[j * 2 + 1] = bpack(__float2bfloat16(v.z - __bfloat162float(h2)),
                             __float2bfloat16(v.w - __bfloat162float(h3)));
    }
    *(uint4*)(Bh + brow * 80 + bk * 2)      = make_uint4(h[0], h[1], h[2], h[3]);
    *(uint4*)(Bh + brow * 80 + bk * 2 + 16) = make_uint4(h[4], h[5], h[6], h[7]);
    *(uint4*)(Bl + brow * 80 + bk * 2)      = make_uint4(l[0], l[1], l[2], l[3]);
    *(uint4*)(Bl + brow * 80 + bk * 2 + 16) = make_uint4(l[4], l[5], l[6], l[7]);
}

__device__ __forceinline__ void gemm_mma_body(
    const __nv_bfloat16* __restrict__ ah, const __nv_bfloat16* __restrict__ al,
    const float* __restrict__ W, float* __restrict__ outp, int k0)
{
    extern __shared__ uint8_t smem[];
    const uint32_t sb = smem_u32(smem);
    const int tid = threadIdx.x, warp = tid >> 5, lane = tid & 31;
    const int j = lane >> 3, r8 = lane & 7;

    float acc[2][2][4];
#pragma unroll
    for (int a = 0; a < 2; a++)
#pragma unroll
        for (int b = 0; b < 2; b++)
#pragma unroll
            for (int q = 0; q < 4; q++) acc[a][b][q] = 0.f;

    WRegs r;
    ldg_chunk(r, ah, al, W, k0);
    sts_chunk(smem, 0, r);
    __syncthreads();

#pragma unroll 1
    for (int c = 0; c < NCH; c++) {
        if (c + 1 < NCH) ldg_chunk(r, ah, al, W, k0 + (c + 1) * KCH);

        const uint32_t Ab = sb + (c & 1) * A_BUF;
        const uint32_t Bb = sb + B_OFF + (c & 1) * B_BUF;
#pragma unroll
        for (int ks = 0; ks < 2; ks++) {
            const uint32_t aaddr = Ab
                + (uint32_t)(((j & 1) * 8 + r8) * 80 + (ks * 2 + (j >> 1)) * 16);
            const uint32_t baddr = Bb
                + (uint32_t)((warp * 16 + (j >> 1) * 8 + r8) * 80
                             + (ks * 2 + (j & 1)) * 16);
            uint32_t f0, f1, f2, f3, g0, g1, g2, g3;
            uint32_t p0, p1, p2, p3, q0, q1, q2, q3;
            uint32_t bh0, bh1, bh2, bh3, bl0, bl1, bl2, bl3;
            ldsm4(f0, f1, f2, f3, aaddr);
            ldsm4(g0, g1, g2, g3, aaddr + 16 * 80);
            ldsm4(p0, p1, p2, p3, aaddr + A_HL);
            ldsm4(q0, q1, q2, q3, aaddr + A_HL + 16 * 80);
            ldsm4(bh0, bh1, bh2, bh3, baddr);
            ldsm4(bl0, bl1, bl2, bl3, baddr + B_HL);

            mma16816(acc[0][0], f0, f1, f2, f3, bh0, bh1);
            mma16816(acc[0][1], f0, f1, f2, f3, bh2, bh3);
            mma16816(acc[1][0], g0, g1, g2, g3, bh0, bh1);
            mma16816(acc[1][1], g0, g1, g2, g3, bh2, bh3);
            mma16816(acc[0][0], f0, f1, f2, f3, bl0, bl1);
            mma16816(acc[0][1], f0, f1, f2, f3, bl2, bl3);
            mma16816(acc[1][0], g0, g1, g2, g3, bl0, bl1);
            mma16816(acc[1][1], g0, g1, g2, g3, bl2, bl3);
            mma16816(acc[0][0], p0, p1, p2, p3, bh0, bh1);
            mma16816(acc[0][1], p0, p1, p2, p3, bh2, bh3);
            mma16816(acc[1][0], q0, q1, q2, q3, bh0, bh1);
            mma16816(acc[1][1], q0, q1, q2, q3, bh2, bh3);
        }
        if (c + 1 < NCH) sts_chunk(smem, (c + 1) & 1, r);
        __syncthreads();
    }

#pragma unroll
    for (int mt = 0; mt < 2; mt++)
#pragma unroll
        for (int nh = 0; nh < 2; nh++) {
            const float* cc = acc[mt][nh];
            const int m0 = mt * 16 + (lane >> 2);
            const int n  = warp * 16 + nh * 8 + (lane & 3) * 2;
            *(float2*)(outp + (size_t)m0 * 128 + n)       = make_float2(cc[0], cc[1]);
            *(float2*)(outp + (size_t)(m0 + 8) * 128 + n) = make_float2(cc[2], cc[3]);
        }
}

__global__ __launch_bounds__(256, 2) void gemm_qkv_mma(
    const float* __restrict__ wq, const float* __restrict__ wk,
    const float* __restrict__ wv)
{
    const int tile = blockIdx.x, slice = blockIdx.y;
    const float* W;
    if (tile < 16)      W = wq + (size_t)tile * 128 * HIDDEN;
    else if (tile < 20) W = wk + (size_t)(tile - 16) * 128 * HIDDEN;
    else                W = wv + (size_t)(tile - 20) * 128 * HIDDEN;
    gemm_mma_body(g_xh, g_xl, W,
                  g_part + (size_t)(tile * KS + slice) * 4096,
                  slice * (HIDDEN / KS));
}

__global__ __launch_bounds__(256, 2) void gemm_o_mma(const float* __restrict__ wo)
{
    const int tile = blockIdx.x, slice = blockIdx.y;
    gemm_mma_body(g_ah, g_al, wo + (size_t)tile * 128 * HIDDEN,
                  g_part + (size_t)(tile * KS + slice) * 4096,
                  slice * (HIDDEN / KS));
}

// ---------------------------------------------------------------------------
__global__ __launch_bounds__(256) void prep_x(const float* __restrict__ x)
{
    const int b = blockIdx.x;
    const int c0 = threadIdx.x * 8;
    const float* xr = x + (size_t)b * HIDDEN + c0;
    uint32_t hp[4], lp[4];
#pragma unroll
    for (int g = 0; g < 2; g++) {
        const float4 v = *(const float4*)(xr + g * 4);
        const __nv_bfloat16 h0 = __float2bfloat16(v.x);
        const __nv_bfloat16 h1 = __float2bfloat16(v.y);
        const __nv_bfloat16 h2 = __float2bfloat16(v.z);
        const __nv_bfloat16 h3 = __float2bfloat16(v.w);
        hp[g * 2 + 0] = bpack(h0, h1);
        hp[g * 2 + 1] = bpack(h2, h3);
        lp[g * 2 + 0] = bpack(__float2bfloat16(v.x - __bfloat162float(h0)),
                              __float2bfloat16(v.y - __bfloat162float(h1)));
        lp[g * 2 + 1] = bpack(__float2bfloat16(v.z - __bfloat162float(h2)),
                              __float2bfloat16(v.w - __bfloat162float(h3)));
    }
    *(uint4*)(g_xh + (size_t)b * HIDDEN + c0) = make_uint4(hp[0], hp[1], hp[2], hp[3]);
    *(uint4*)(g_xl + (size_t)b * HIDDEN + c0) = make_uint4(lp[0], lp[1], lp[2], lp[3]);
}

// ---------------------------------------------------------------------------
__global__ __launch_bounds__(128) void reduce_norm_rope(
    const float* __restrict__ position,
    const float* __restrict__ qnw, const float* __restrict__ knw)
{
    const int head = blockIdx.x, b = blockIdx.y, d = threadIdx.x;
    const size_t base = (size_t)head * KS * 4096 + (size_t)b * 128 + d;
    float v = 0.f;
#pragma unroll
    for (int s = 0; s < KS; s++) v += g_part[base + (size_t)s * 4096];

    if (head >= 20) {
        g_v[(b * NKV + head - 20) * HDIM + d] = v;
        return;
    }

    __shared__ float red[4];
    __shared__ float sv[128];

    float sq = v * v;
#pragma unroll
    for (int off = 16; off; off >>= 1)
        sq += __shfl_xor_sync(0xffffffffu, sq, off);
    if ((d & 31) == 0) red[d >> 5] = sq;
    __syncthreads();
    const float ssq  = red[0] + red[1] + red[2] + red[3];
    const float norm = rsqrtf(ssq * (1.f / 128.f) + EPSV);
    const float nv   = v * norm * ((head < 16) ? qnw[d] : knw[d]);
    sv[d] = nv;
    __syncthreads();

    const float pos = position[0];
    const int   jj  = d & 63;
    const float fr  = pos * exp2f((float)jj * (-19.93156856932417f / 64.f));
    float c, s;
    sincosf(fr, &s, &c);
    const float other = (d < 64) ? sv[d + 64] : sv[d - 64];
    const float out   = (d < 64) ? (nv * c - other * s)
                                 : (nv * c + other * s);
    if (head < 16) g_q[(b * NHEADS + head) * HDIM + d] = out * QSCALE;
    else           g_k[(b * NKV + head - 16) * HDIM + d] = out;
}

// ---------------------------------------------------------------------------
// Attention partial v2: 8-row unroll, 6-shuffle packed head reduction,
// fresh-KV row hoisted out of the hot loops. Block (kv, b, split c) x 256.
// ---------------------------------------------------------------------------
__global__ __launch_bounds__(256) void attn_part(
    const float* __restrict__ k_cache, const float* __restrict__ v_cache,
    const float* __restrict__ position)
{
    const int kv = blockIdx.x, b = blockIdx.y, c = blockIdx.z;
    const int tid = threadIdx.x;
    const int lane = tid & 31, w = tid >> 5;
    const int pos = (int)position[0];
    const int S   = pos + 1;
    const int LEN = (S + NSPLIT - 1) / NSPLIT;
    const int lo  = c * LEN;
    const int hi  = min(S, lo + LEN);
    const int hic = min(hi, pos);            // cache-only rows [lo, hic)
    const bool has_new = (pos >= lo) && (pos < hi);
    const int myh = lane & 3;

    __shared__ float q_s[4][HDIM];
    __shared__ float sc[4][(MAXSEQ + NSPLIT - 1) / NSPLIT + 4];
    __shared__ float wred[8][4];
    __shared__ float gm[4];
    __shared__ float wout[8][4][HDIM];

    for (int i = tid; i < 4 * HDIM; i += 256) {
        const int h = i >> 7, d = i & 127;
        q_s[h][d] = g_q[(b * NHEADS + kv * 4 + h) * HDIM + d];
    }
    __syncthreads();

    float qr[4][4];
#pragma unroll
    for (int h = 0; h < 4; h++)
#pragma unroll
        for (int jj = 0; jj < 4; jj++) qr[h][jj] = q_s[h][lane * 4 + jj];

    const float* kbase = k_cache + (size_t)(b * NKV + kv) * MAXSEQ * HDIM + lane * 4;
    const float* knew  = g_k + (b * NKV + kv) * HDIM;

    float wm = -1e30f;     // per-lane running max for head (lane&3)

    // ---- phase 1: scores over cache rows, 8-row unroll ---------------------
    for (int s0 = lo + w * 8; s0 < hic; s0 += 64) {
        float4 r[8];
        const float* kp = kbase + (size_t)s0 * HDIM;
#pragma unroll
        for (int u = 0; u < 8; u++)
            if (s0 + u < hic) r[u] = *(const float4*)(kp + (size_t)u * HDIM);
#pragma unroll
        for (int u = 0; u < 8; u++) {
            if (s0 + u < hic) {
                const float v0 = fmaf(r[u].x, qr[0][0], fmaf(r[u].y, qr[0][1],
                                 fmaf(r[u].z, qr[0][2], r[u].w * qr[0][3])));
                const float v1 = fmaf(r[u].x, qr[1][0], fmaf(r[u].y, qr[1][1],
                                 fmaf(r[u].z, qr[1][2], r[u].w * qr[1][3])));
                const float v2 = fmaf(r[u].x, qr[2][0], fmaf(r[u].y, qr[2][1],
                                 fmaf(r[u].z, qr[2][2], r[u].w * qr[2][3])));
                const float v3 = fmaf(r[u].x, qr[3][0], fmaf(r[u].y, qr[3][1],
                                 fmaf(r[u].z, qr[3][2], r[u].w * qr[3][3])));
                const float p = reduce4(v0, v1, v2, v3, lane);
                wm = fmaxf(wm, p);
                if (lane < 4) sc[lane][s0 + u - lo] = p;
            }
        }
    }
    // fresh-K row (warp 0 only)
    if (has_new && w == 0) {
        const float4 r = *(const float4*)(knew + lane * 4);
        const float v0 = fmaf(r.x, qr[0][0], fmaf(r.y, qr[0][1],
                         fmaf(r.z, qr[0][2], r.w * qr[0][3])));
        const float v1 = fmaf(r.x, qr[1][0], fmaf(r.y, qr[1][1],
                         fmaf(r.z, qr[1][2], r.w * qr[1][3])));
        const float v2 = fmaf(r.x, qr[2][0], fmaf(r.y, qr[2][1],
                         fmaf(r.z, qr[2][2], r.w * qr[2][3])));
        const float v3 = fmaf(r.x, qr[3][0], fmaf(r.y, qr[3][1],
                         fmaf(r.z, qr[3][2], r.w * qr[3][3])));
        const float p = reduce4(v0, v1, v2, v3, lane);
        wm = fmaxf(wm, p);
        if (lane < 4) sc[lane][pos - lo] = p;
    }
    if (lane < 4) wred[w][lane] = wm;
    __syncthreads();
    if (tid < 4) {
        float m = wred[0][tid];
#pragma unroll
        for (int i = 1; i < 8; i++) m = fmaxf(m, wred[i][tid]);
        gm[tid] = m;
    }
    __syncthreads();

    // ---- phase 2: exp + partial sums ---------------------------------------
    const int nrows = hi - lo;
    float lsum[4] = {0.f, 0.f, 0.f, 0.f};
#pragma unroll
    for (int h = 0; h < 4; h++) {
        const float m = gm[h];
        for (int i = tid; i < nrows; i += 256) {
            const float e = __expf(sc[h][i] - m);
            sc[h][i] = e;
            lsum[h] += e;
        }
    }
#pragma unroll
    for (int h = 0; h < 4; h++) {
        float v = lsum[h];
#pragma unroll
        for (int off = 16; off; off >>= 1)
            v += __shfl_xor_sync(0xffffffffu, v, off);
        if (lane == 0) wred[w][h] = v;
    }
    __syncthreads();
    if (tid < 4) {
        float v = 0.f;
#pragma unroll
        for (int i = 0; i < 8; i++) v += wred[i][tid];
        const int pbase = ((b * NKV + kv) * NSPLIT + c) * 4 + tid;
        g_ps[pbase] = v;
        g_pm[pbase] = gm[tid];
    }

    // ---- phase 3: P @ V, 8-row unroll --------------------------------------
    const float* vbase = v_cache + (size_t)(b * NKV + kv) * MAXSEQ * HDIM + lane * 4;
    const float* vnew  = g_v + (b * NKV + kv) * HDIM;
    float acc[4][4];
#pragma unroll
    for (int h = 0; h < 4; h++)
#pragma unroll
        for (int jj = 0; jj < 4; jj++) acc[h][jj] = 0.f;
    __syncthreads();

    for (int s0 = lo + w * 8; s0 < hic; s0 += 64) {
        float4 r[8];
        const float* vp = vbase + (size_t)s0 * HDIM;
#pragma unroll
        for (int u = 0; u < 8; u++)
            if (s0 + u < hic) r[u] = *(const float4*)(vp + (size_t)u * HDIM);
#pragma unroll
        for (int u = 0; u < 8; u++) {
            if (s0 + u < hic) {
                const int i = s0 + u - lo;
                const float p0 = sc[0][i], p1 = sc[1][i];
                const float p2 = sc[2][i], p3 = sc[3][i];
                acc[0][0] = fmaf(p0, r[u].x, acc[0][0]);
                acc[0][1] = fmaf(p0, r[u].y, acc[0][1]);
                acc[0][2] = fmaf(p0, r[u].z, acc[0][2]);
                acc[0][3] = fmaf(p0, r[u].w, acc[0][3]);
                acc[1][0] = fmaf(p1, r[u].x, acc[1][0]);
                acc[1][1] = fmaf(p1, r[u].y, acc[1][1]);
                acc[1][2] = fmaf(p1, r[u].z, acc[1][2]);
                acc[1][3] = fmaf(p1, r[u].w, acc[1][3]);
                acc[2][0] = fmaf(p2, r[u].x, acc[2][0]);
                acc[2][1] = fmaf(p2, r[u].y, acc[2][1]);
                acc[2][2] = fmaf(p2, r[u].z, acc[2][2]);
                acc[2][3] = fmaf(p2, r[u].w, acc[2][3]);
                acc[3][0] = fmaf(p3, r[u].x, acc[3][0]);
                acc[3][1] = fmaf(p3, r[u].y, acc[3][1]);
                acc[3][2] = fmaf(p3, r[u].z, acc[3][2]);
                acc[3][3] = fmaf(p3, r[u].w, acc[3][3]);
            }
        }
    }
    if (has_new && w == 0) {
        const float4 r = *(const float4*)(vnew + lane * 4);
        const int i = pos - lo;
        const float p0 = sc[0][i], p1 = sc[1][i];
        const float p2 = sc[2][i], p3 = sc[3][i];
        acc[0][0] = fmaf(p0, r.x, acc[0][0]);
        acc[0][1] = fmaf(p0, r.y, acc[0][1]);
        acc[0][2] = fmaf(p0, r.z, acc[0][2]);
        acc[0][3] = fmaf(p0, r.w, acc[0][3]);
        acc[1][0] = fmaf(p1, r.x, acc[1][0]);
        acc[1][1] = fmaf(p1, r.y, acc[1][1]);
        acc[1][2] = fmaf(p1, r.z, acc[1][2]);
        acc[1][3] = fmaf(p1, r.w, acc[1][3]);
        acc[2][0] = fmaf(p2, r.x, acc[2][0]);
        acc[2][1] = fmaf(p2, r.y, acc[2][1]);
        acc[2][2] = fmaf(p2, r.z, acc[2][2]);
        acc[2][3] = fmaf(p2, r.w, acc[2][3]);
        acc[3][0] = fmaf(p3, r.x, acc[3][0]);
        acc[3][1] = fmaf(p3, r.y, acc[3][1]);
        acc[3][2] = fmaf(p3, r.z, acc[3][2]);
        acc[3][3] = fmaf(p3, r.w, acc[3][3]);
    }
#pragma unroll
    for (int h = 0; h < 4; h++)
#pragma unroll
        for (int jj = 0; jj < 4; jj++)
            wout[w][h][lane * 4 + jj] = acc[h][jj];
    __syncthreads();

    for (int i = tid; i < 4 * HDIM; i += 256) {
        const int h = i >> 7, d = i & 127;
        float v = 0.f;
#pragma unroll
        for (int ww = 0; ww < 8; ww++) v += wout[ww][h][d];
        g_pa[(((size_t)(b * NKV + kv) * NSPLIT + c) * 4 + h) * HDIM + d] = v;
    }
}

// ---------------------------------------------------------------------------
__global__ __launch_bounds__(128) void combine_conv()
{
    const int hidx = blockIdx.x, b = blockIdx.y, d = threadIdx.x;
    const int kv = hidx >> 2, h = hidx & 3;
    const int pb = ((b * NKV + kv) * NSPLIT) * 4 + h;

    float m = -1e30f;
#pragma unroll
    for (int c = 0; c < NSPLIT; c++) m = fmaxf(m, g_pm[pb + c * 4]);
    float den = 0.f, wc[NSPLIT];
#pragma unroll
    for (int c = 0; c < NSPLIT; c++) {
        wc[c] = __expf(g_pm[pb + c * 4] - m);
        den   = fmaf(g_ps[pb + c * 4], wc[c], den);
    }
    const float inv = 1.f / den;

    float val = 0.f;
#pragma unroll
    for (int c = 0; c < NSPLIT; c++)
        val = fmaf(wc[c],
                   g_pa[(size_t)(((b * NKV + kv) * NSPLIT + c) * 4 + h) * HDIM + d],
                   val);
    const float r = val * inv;
    const __nv_bfloat16 hv = __float2bfloat16(r);
    const __nv_bfloat16 lv = __float2bfloat16(r - __bfloat162float(hv));
    g_ah[(size_t)b * HIDDEN + hidx * 128 + d] = hv;
    g_al[(size_t)b * HIDDEN + hidx * 128 + d] = lv;
}

__global__ __launch_bounds__(128) void reduce_out(float* __restrict__ out)
{
    const int tile = blockIdx.x, b = blockIdx.y, d = threadIdx.x;
    const size_t base = (size_t)tile * KS * 4096 + (size_t)b * 128 + d;
    float v = 0.f;
#pragma unroll
    for (int s = 0; s < KS; s++) v += g_part[base + (size_t)s * 4096];
    out[b * HIDDEN + tile * 128 + d] = v;
}

// ---------------------------------------------------------------------------
extern "C" void kernel_launch(void* const* d_in, const int* in_sizes, int n_in,
                              void* d_out, int out_size)
{
    const float* x        = (const float*)d_in[0];
    const float* position = (const float*)d_in[1];
    const float* k_cache  = (const float*)d_in[3];
    const float* v_cache  = (const float*)d_in[4];
    const float* wq       = (const float*)d_in[6];
    const float* wk       = (const float*)d_in[7];
    const float* wv       = (const float*)d_in[8];
    const float* wo       = (const float*)d_in[9];
    const float* qnw      = (const float*)d_in[10];
    const float* knw      = (const float*)d_in[11];
    float* out            = (float*)d_out;

    cudaFuncSetAttribute(gemm_qkv_mma, cudaFuncAttributeMaxDynamicSharedMemorySize, SMEM_MMA);
    cudaFuncSetAttribute(gemm_o_mma,   cudaFuncAttributeMaxDynamicSharedMemorySize, SMEM_MMA);

    prep_x<<<32, 256>>>(x);
    gemm_qkv_mma<<<dim3(24, KS), 256, SMEM_MMA>>>(wq, wk, wv);
    reduce_norm_rope<<<dim3(24, 32), 128>>>(position, qnw, knw);
    attn_part<<<dim3(NKV, 32, NSPLIT), 256>>>(k_cache, v_cache, position);
    combine_conv<<<dim3(16, 32), 128>>>();
    gemm_o_mma<<<dim3(16, KS), 256, SMEM_MMA>>>(wo);
    reduce_out<<<dim3(16, 32), 128>>>(out);
}

// round 8
// speedup vs baseline: 1.2506x; 1.0245x over previous
#include <cuda_runtime.h>
#include <cuda_bf16.h>
#include <cstdint>
#include <math.h>

#define NHEADS   16
#define NKV      4
#define HDIM     128
#define HIDDEN   2048
#define MAXSEQ   1024
#define EPSV     1e-6f
#define QSCALE   0.088388347648318447f   /* 1/sqrt(128) */
#define NSPLIT   8                       /* attention seq split */
#define KS       8                       /* GEMM k-split */
#define KCH      32                      /* k per staged chunk */
#define NCH      ((HIDDEN / KS) / KCH)   /* 8 chunks per block */

// smem layout (dynamic, 51200 B): A[2buf][2hl][32][80B], B[2buf][2hl][128][80B]
#define A_HL   2560
#define A_BUF  5120
#define B_OFF  10240
#define B_HL   10240
#define B_BUF  20480
#define SMEM_MMA 51200

// ---------------- scratch ---------------------------------------------------
__device__ __align__(16) float g_part[24 * KS * 32 * 128];
__device__ __align__(16) __nv_bfloat16 g_xh[32 * HIDDEN];
__device__ __align__(16) __nv_bfloat16 g_xl[32 * HIDDEN];
__device__ __align__(16) __nv_bfloat16 g_ah[32 * HIDDEN];
__device__ __align__(16) __nv_bfloat16 g_al[32 * HIDDEN];
__device__ __align__(16) float g_q[32 * NHEADS * HDIM];
__device__ __align__(16) float g_k[32 * NKV * HDIM];
__device__ __align__(16) float g_v[32 * NKV * HDIM];
__device__ __align__(16) float g_pa[32 * NKV * NSPLIT * 4 * HDIM];
__device__ float g_pm[32 * NKV * NSPLIT * 4];
__device__ float g_ps[32 * NKV * NSPLIT * 4];

// ---------------- wrappers ---------------------------------------------------
__device__ __forceinline__ uint32_t smem_u32(const void* p) {
    uint32_t a;
    asm("{ .reg .u64 t; cvta.to.shared.u64 t, %1; cvt.u32.u64 %0, t; }"
        : "=r"(a) : "l"(p));
    return a;
}
__device__ __forceinline__ void ldsm4(uint32_t& r0, uint32_t& r1,
                                      uint32_t& r2, uint32_t& r3, uint32_t a) {
    asm volatile("ldmatrix.sync.aligned.m8n8.x4.shared.b16 {%0,%1,%2,%3}, [%4];"
                 : "=r"(r0), "=r"(r1), "=r"(r2), "=r"(r3) : "r"(a));
}
__device__ __forceinline__ void mma16816(float* c,
                                         uint32_t a0, uint32_t a1, uint32_t a2,
                                         uint32_t a3, uint32_t b0, uint32_t b1) {
    asm volatile(
        "mma.sync.aligned.m16n8k16.row.col.f32.bf16.bf16.f32 "
        "{%0,%1,%2,%3}, {%4,%5,%6,%7}, {%8,%9}, {%0,%1,%2,%3};"
        : "+f"(c[0]), "+f"(c[1]), "+f"(c[2]), "+f"(c[3])
        : "r"(a0), "r"(a1), "r"(a2), "r"(a3), "r"(b0), "r"(b1));
}
__device__ __forceinline__ uint32_t bpack(__nv_bfloat16 a, __nv_bfloat16 b) {
    __nv_bfloat162 t = __halves2bfloat162(a, b);
    return *(uint32_t*)&t;
}

// 4-head packed butterfly: lane l ends with the full 128-dim dot for head l&3.
__device__ __forceinline__ float reduce4(float v0, float v1, float v2, float v3,
                                         int lane)
{
    const bool b0 = lane & 1, b1 = lane & 2;
    float x = b0 ? v1 : v0;
    float y = b0 ? v0 : v1;
    x += __shfl_xor_sync(0xffffffffu, y, 1);
    float z = b0 ? v3 : v2;
    float u = b0 ? v2 : v3;
    z += __shfl_xor_sync(0xffffffffu, u, 1);
    float p = b1 ? z : x;
    float q = b1 ? x : z;
    p += __shfl_xor_sync(0xffffffffu, q, 2);
    p += __shfl_xor_sync(0xffffffffu, p, 4);
    p += __shfl_xor_sync(0xffffffffu, p, 8);
    p += __shfl_xor_sync(0xffffffffu, p, 16);
    return p;
}

// ---------------- GEMM staging (unchanged) ----------------------------------
struct WRegs {
    float4 v[4];
    uint2  ah, al;
};

__device__ __forceinline__ void ldg_chunk(WRegs& r,
    const __nv_bfloat16* __restrict__ ah, const __nv_bfloat16* __restrict__ al,
    const float* __restrict__ W, int k0)
{
    const int tid  = threadIdx.x;
    const int arow = tid >> 3, akq = (tid & 7) * 4;
    r.ah = *(const uint2*)(ah + (size_t)arow * HIDDEN + k0 + akq);
    r.al = *(const uint2*)(al + (size_t)arow * HIDDEN + k0 + akq);
    const int brow = tid >> 1, bk = (tid & 1) * 16;
#pragma unroll
    for (int j = 0; j < 4; j++)
        r.v[j] = *(const float4*)(W + (size_t)brow * HIDDEN + k0 + bk + j * 4);
}

__device__ __forceinline__ void sts_chunk(uint8_t* smem, int buf, const WRegs& r)
{
    const int tid  = threadIdx.x;
    const int arow = tid >> 3, akq = (tid & 7) * 4;
    uint8_t* A = smem + buf * A_BUF;
    *(uint2*)(A + arow * 80 + akq * 2)        = r.ah;
    *(uint2*)(A + A_HL + arow * 80 + akq * 2) = r.al;

    const int brow = tid >> 1, bk = (tid & 1) * 16;
    uint8_t* Bh = smem + B_OFF + buf * B_BUF;
    uint8_t* Bl = Bh + B_HL;
    uint32_t h[8], l[8];
#pragma unroll
    for (int j = 0; j < 4; j++) {
        const float4 v = r.v[j];
        const __nv_bfloat16 h0 = __float2bfloat16(v.x);
        const __nv_bfloat16 h1 = __float2bfloat16(v.y);
        const __nv_bfloat16 h2 = __float2bfloat16(v.z);
        const __nv_bfloat16 h3 = __float2bfloat16(v.w);
        h[j * 2 + 0] = bpack(h0, h1);
        h[j * 2 + 1] = bpack(h2, h3);
        l[j * 2 + 0] = bpack(__float2bfloat16(v.x - __bfloat162float(h0)),
                             __float2bfloat16(v.y - __bfloat162float(h1)));
        l[j * 2 + 1] = bpack(__float2bfloat16(v.z - __bfloat162float(h2)),
                             __float2bfloat16(v.w - __bfloat162float(h3)));
    }
    *(uint4*)(Bh + brow * 80 + bk * 2)      = make_uint4(h[0], h[1], h[2], h[3]);
    *(uint4*)(Bh + brow * 80 + bk * 2 + 16) = make_uint4(h[4], h[5], h[6], h[7]);
    *(uint4*)(Bl + brow * 80 + bk * 2)      = make_uint4(l[0], l[1], l[2], l[3]);
    *(uint4*)(Bl + brow * 80 + bk * 2 + 16) = make_uint4(l[4], l[5], l[6], l[7]);
}

__device__ __forceinline__ void gemm_mma_body(
    const __nv_bfloat16* __restrict__ ah, const __nv_bfloat16* __restrict__ al,
    const float* __restrict__ W, float* __restrict__ outp, int k0)
{
    extern __shared__ uint8_t smem[];
    const uint32_t sb = smem_u32(smem);
    const int tid = threadIdx.x, warp = tid >> 5, lane = tid & 31;
    const int j = lane >> 3, r8 = lane & 7;

    float acc[2][2][4];
#pragma unroll
    for (int a = 0; a < 2; a++)
#pragma unroll
        for (int b = 0; b < 2; b++)
#pragma unroll
            for (int q = 0; q < 4; q++) acc[a][b][q] = 0.f;

    WRegs r;
    ldg_chunk(r, ah, al, W, k0);
    sts_chunk(smem, 0, r);
    __syncthreads();

#pragma unroll 1
    for (int c = 0; c < NCH; c++) {
        if (c + 1 < NCH) ldg_chunk(r, ah, al, W, k0 + (c + 1) * KCH);

        const uint32_t Ab = sb + (c & 1) * A_BUF;
        const uint32_t Bb = sb + B_OFF + (c & 1) * B_BUF;
#pragma unroll
        for (int ks = 0; ks < 2; ks++) {
            const uint32_t aaddr = Ab
                + (uint32_t)(((j & 1) * 8 + r8) * 80 + (ks * 2 + (j >> 1)) * 16);
            const uint32_t baddr = Bb
                + (uint32_t)((warp * 16 + (j >> 1) * 8 + r8) * 80
                             + (ks * 2 + (j & 1)) * 16);
            uint32_t f0, f1, f2, f3, g0, g1, g2, g3;
            uint32_t p0, p1, p2, p3, q0, q1, q2, q3;
            uint32_t bh0, bh1, bh2, bh3, bl0, bl1, bl2, bl3;
            ldsm4(f0, f1, f2, f3, aaddr);
            ldsm4(g0, g1, g2, g3, aaddr + 16 * 80);
            ldsm4(p0, p1, p2, p3, aaddr + A_HL);
            ldsm4(q0, q1, q2, q3, aaddr + A_HL + 16 * 80);
            ldsm4(bh0, bh1, bh2, bh3, baddr);
            ldsm4(bl0, bl1, bl2, bl3, baddr + B_HL);

            mma16816(acc[0][0], f0, f1, f2, f3, bh0, bh1);
            mma16816(acc[0][1], f0, f1, f2, f3, bh2, bh3);
            mma16816(acc[1][0], g0, g1, g2, g3, bh0, bh1);
            mma16816(acc[1][1], g0, g1, g2, g3, bh2, bh3);
            mma16816(acc[0][0], f0, f1, f2, f3, bl0, bl1);
            mma16816(acc[0][1], f0, f1, f2, f3, bl2, bl3);
            mma16816(acc[1][0], g0, g1, g2, g3, bl0, bl1);
            mma16816(acc[1][1], g0, g1, g2, g3, bl2, bl3);
            mma16816(acc[0][0], p0, p1, p2, p3, bh0, bh1);
            mma16816(acc[0][1], p0, p1, p2, p3, bh2, bh3);
            mma16816(acc[1][0], q0, q1, q2, q3, bh0, bh1);
            mma16816(acc[1][1], q0, q1, q2, q3, bh2, bh3);
        }
        if (c + 1 < NCH) sts_chunk(smem, (c + 1) & 1, r);
        __syncthreads();
    }

#pragma unroll
    for (int mt = 0; mt < 2; mt++)
#pragma unroll
        for (int nh = 0; nh < 2; nh++) {
            const float* cc = acc[mt][nh];
            const int m0 = mt * 16 + (lane >> 2);
            const int n  = warp * 16 + nh * 8 + (lane & 3) * 2;
            *(float2*)(outp + (size_t)m0 * 128 + n)       = make_float2(cc[0], cc[1]);
            *(float2*)(outp + (size_t)(m0 + 8) * 128 + n) = make_float2(cc[2], cc[3]);
        }
}

__global__ __launch_bounds__(256, 2) void gemm_qkv_mma(
    const float* __restrict__ wq, const float* __restrict__ wk,
    const float* __restrict__ wv)
{
    const int tile = blockIdx.x, slice = blockIdx.y;
    const float* W;
    if (tile < 16)      W = wq + (size_t)tile * 128 * HIDDEN;
    else if (tile < 20) W = wk + (size_t)(tile - 16) * 128 * HIDDEN;
    else                W = wv + (size_t)(tile - 20) * 128 * HIDDEN;
    gemm_mma_body(g_xh, g_xl, W,
                  g_part + (size_t)(tile * KS + slice) * 4096,
                  slice * (HIDDEN / KS));
}

__global__ __launch_bounds__(256, 2) void gemm_o_mma(const float* __restrict__ wo)
{
    const int tile = blockIdx.x, slice = blockIdx.y;
    gemm_mma_body(g_ah, g_al, wo + (size_t)tile * 128 * HIDDEN,
                  g_part + (size_t)(tile * KS + slice) * 4096,
                  slice * (HIDDEN / KS));
}

// ---------------------------------------------------------------------------
__global__ __launch_bounds__(256) void prep_x(const float* __restrict__ x)
{
    const int b = blockIdx.x;
    const int c0 = threadIdx.x * 8;
    const float* xr = x + (size_t)b * HIDDEN + c0;
    uint32_t hp[4], lp[4];
#pragma unroll
    for (int g = 0; g < 2; g++) {
        const float4 v = *(const float4*)(xr + g * 4);
        const __nv_bfloat16 h0 = __float2bfloat16(v.x);
        const __nv_bfloat16 h1 = __float2bfloat16(v.y);
        const __nv_bfloat16 h2 = __float2bfloat16(v.z);
        const __nv_bfloat16 h3 = __float2bfloat16(v.w);
        hp[g * 2 + 0] = bpack(h0, h1);
        hp[g * 2 + 1] = bpack(h2, h3);
        lp[g * 2 + 0] = bpack(__float2bfloat16(v.x - __bfloat162float(h0)),
                              __float2bfloat16(v.y - __bfloat162float(h1)));
        lp[g * 2 + 1] = bpack(__float2bfloat16(v.z - __bfloat162float(h2)),
                              __float2bfloat16(v.w - __bfloat162float(h3)));
    }
    *(uint4*)(g_xh + (size_t)b * HIDDEN + c0) = make_uint4(hp[0], hp[1], hp[2], hp[3]);
    *(uint4*)(g_xl + (size_t)b * HIDDEN + c0) = make_uint4(lp[0], lp[1], lp[2], lp[3]);
}

// ---------------------------------------------------------------------------
__global__ __launch_bounds__(128) void reduce_norm_rope(
    const float* __restrict__ position,
    const float* __restrict__ qnw, const float* __restrict__ knw)
{
    const int head = blockIdx.x, b = blockIdx.y, d = threadIdx.x;
    const size_t base = (size_t)head * KS * 4096 + (size_t)b * 128 + d;
    float v = 0.f;
#pragma unroll
    for (int s = 0; s < KS; s++) v += g_part[base + (size_t)s * 4096];

    if (head >= 20) {
        g_v[(b * NKV + head - 20) * HDIM + d] = v;
        return;
    }

    __shared__ float red[4];
    __shared__ float sv[128];

    float sq = v * v;
#pragma unroll
    for (int off = 16; off; off >>= 1)
        sq += __shfl_xor_sync(0xffffffffu, sq, off);
    if ((d & 31) == 0) red[d >> 5] = sq;
    __syncthreads();
    const float ssq  = red[0] + red[1] + red[2] + red[3];
    const float norm = rsqrtf(ssq * (1.f / 128.f) + EPSV);
    const float nv   = v * norm * ((head < 16) ? qnw[d] : knw[d]);
    sv[d] = nv;
    __syncthreads();

    const float pos = position[0];
    const int   jj  = d & 63;
    const float fr  = pos * exp2f((float)jj * (-19.93156856932417f / 64.f));
    float c, s;
    sincosf(fr, &s, &c);
    const float other = (d < 64) ? sv[d + 64] : sv[d - 64];
    const float out   = (d < 64) ? (nv * c - other * s)
                                 : (nv * c + other * s);
    if (head < 16) g_q[(b * NHEADS + head) * HDIM + d] = out * QSCALE;
    else           g_k[(b * NKV + head - 16) * HDIM + d] = out;
}

// ---------------------------------------------------------------------------
// Attention partial v3: single streaming pass, no max subtraction (scores are
// Cauchy-Schwarz bounded by ~11.3 since ||q*QSCALE||=1, so exp() is safe in
// fp32 and the common scale cancels in the softmax division).
// Block (kv, b, split c) x 128 threads (4 warps).
// Lane l accumulates heads in order (l&3)^j for j=0..3.
// ---------------------------------------------------------------------------
__global__ __launch_bounds__(128) void attn_part(
    const float* __restrict__ k_cache, const float* __restrict__ v_cache,
    const float* __restrict__ position)
{
    const int kv = blockIdx.x, b = blockIdx.y, c = blockIdx.z;
    const int tid = threadIdx.x;
    const int lane = tid & 31, w = tid >> 5;
    const int myh = lane & 3;
    const int pos = (int)position[0];
    const int S   = pos + 1;
    const int LEN = (S + NSPLIT - 1) / NSPLIT;
    const int lo  = c * LEN;
    const int hi  = min(S, lo + LEN);
    const int hic = min(hi, pos);            // cache-only rows
    const bool has_new = (pos >= lo) && (pos < hi);

    __shared__ float q_s[4][HDIM];
    __shared__ float wred[4][4];
    __shared__ float wout[4][4][HDIM];

    for (int i = tid; i < 4 * HDIM; i += 128) {
        const int h = i >> 7, d = i & 127;
        q_s[h][d] = g_q[(b * NHEADS + kv * 4 + h) * HDIM + d];
    }
    __syncthreads();

    float qr[4][4];
#pragma unroll
    for (int h = 0; h < 4; h++)
#pragma unroll
        for (int jj = 0; jj < 4; jj++) qr[h][jj] = q_s[h][lane * 4 + jj];

    const float* kbase = k_cache + (size_t)(b * NKV + kv) * MAXSEQ * HDIM + lane * 4;
    const float* vbase = v_cache + (size_t)(b * NKV + kv) * MAXSEQ * HDIM + lane * 4;
    const float* knew  = g_k + (b * NKV + kv) * HDIM;
    const float* vnew  = g_v + (b * NKV + kv) * HDIM;

    // acc[j] = accumulator for head myh^j, dims [lane*4, lane*4+4)
    float acc[4][4];
#pragma unroll
    for (int j = 0; j < 4; j++)
#pragma unroll
        for (int q = 0; q < 4; q++) acc[j][q] = 0.f;
    float lsum = 0.f;                        // expsum for head myh

    for (int s0 = lo + w * 4; s0 < hic; s0 += 16) {
        float4 rk[4], rv[4];
        const float* kp = kbase + (size_t)s0 * HDIM;
        const float* vp = vbase + (size_t)s0 * HDIM;
#pragma unroll
        for (int u = 0; u < 4; u++)
            if (s0 + u < hic) {
                rk[u] = *(const float4*)(kp + (size_t)u * HDIM);
                rv[u] = *(const float4*)(vp + (size_t)u * HDIM);
            }
#pragma unroll
        for (int u = 0; u < 4; u++) {
            if (s0 + u < hic) {
                const float v0 = fmaf(rk[u].x, qr[0][0], fmaf(rk[u].y, qr[0][1],
                                 fmaf(rk[u].z, qr[0][2], rk[u].w * qr[0][3])));
                const float v1 = fmaf(rk[u].x, qr[1][0], fmaf(rk[u].y, qr[1][1],
                                 fmaf(rk[u].z, qr[1][2], rk[u].w * qr[1][3])));
                const float v2 = fmaf(rk[u].x, qr[2][0], fmaf(rk[u].y, qr[2][1],
                                 fmaf(rk[u].z, qr[2][2], rk[u].w * qr[2][3])));
                const float v3 = fmaf(rk[u].x, qr[3][0], fmaf(rk[u].y, qr[3][1],
                                 fmaf(rk[u].z, qr[3][2], rk[u].w * qr[3][3])));
                const float p = reduce4(v0, v1, v2, v3, lane);
                const float e = __expf(p);       // head myh
                lsum += e;
                const float e1 = __shfl_xor_sync(0xffffffffu, e, 1); // myh^1
                const float e2 = __shfl_xor_sync(0xffffffffu, e, 2); // myh^2
                const float e3 = __shfl_xor_sync(0xffffffffu, e, 3); // myh^3
                acc[0][0] = fmaf(e,  rv[u].x, acc[0][0]);
                acc[0][1] = fmaf(e,  rv[u].y, acc[0][1]);
                acc[0][2] = fmaf(e,  rv[u].z, acc[0][2]);
                acc[0][3] = fmaf(e,  rv[u].w, acc[0][3]);
                acc[1][0] = fmaf(e1, rv[u].x, acc[1][0]);
                acc[1][1] = fmaf(e1, rv[u].y, acc[1][1]);
                acc[1][2] = fmaf(e1, rv[u].z, acc[1][2]);
                acc[1][3] = fmaf(e1, rv[u].w, acc[1][3]);
                acc[2][0] = fmaf(e2, rv[u].x, acc[2][0]);
                acc[2][1] = fmaf(e2, rv[u].y, acc[2][1]);
                acc[2][2] = fmaf(e2, rv[u].z, acc[2][2]);
                acc[2][3] = fmaf(e2, rv[u].w, acc[2][3]);
                acc[3][0] = fmaf(e3, rv[u].x, acc[3][0]);
                acc[3][1] = fmaf(e3, rv[u].y, acc[3][1]);
                acc[3][2] = fmaf(e3, rv[u].z, acc[3][2]);
                acc[3][3] = fmaf(e3, rv[u].w, acc[3][3]);
            }
        }
    }
    // fresh-KV row (warp 0 only; warp-uniform predicate)
    if (has_new && w == 0) {
        const float4 rk = *(const float4*)(knew + lane * 4);
        const float4 rv = *(const float4*)(vnew + lane * 4);
        const float v0 = fmaf(rk.x, qr[0][0], fmaf(rk.y, qr[0][1],
                         fmaf(rk.z, qr[0][2], rk.w * qr[0][3])));
        const float v1 = fmaf(rk.x, qr[1][0], fmaf(rk.y, qr[1][1],
                         fmaf(rk.z, qr[1][2], rk.w * qr[1][3])));
        const float v2 = fmaf(rk.x, qr[2][0], fmaf(rk.y, qr[2][1],
                         fmaf(rk.z, qr[2][2], rk.w * qr[2][3])));
        const float v3 = fmaf(rk.x, qr[3][0], fmaf(rk.y, qr[3][1],
                         fmaf(rk.z, qr[3][2], rk.w * qr[3][3])));
        const float p = reduce4(v0, v1, v2, v3, lane);
        const float e = __expf(p);
        lsum += e;
        const float e1 = __shfl_xor_sync(0xffffffffu, e, 1);
        const float e2 = __shfl_xor_sync(0xffffffffu, e, 2);
        const float e3 = __shfl_xor_sync(0xffffffffu, e, 3);
        acc[0][0] = fmaf(e,  rv.x, acc[0][0]);
        acc[0][1] = fmaf(e,  rv.y, acc[0][1]);
        acc[0][2] = fmaf(e,  rv.z, acc[0][2]);
        acc[0][3] = fmaf(e,  rv.w, acc[0][3]);
        acc[1][0] = fmaf(e1, rv.x, acc[1][0]);
        acc[1][1] = fmaf(e1, rv.y, acc[1][1]);
        acc[1][2] = fmaf(e1, rv.z, acc[1][2]);
        acc[1][3] = fmaf(e1, rv.w, acc[1][3]);
        acc[2][0] = fmaf(e2, rv.x, acc[2][0]);
        acc[2][1] = fmaf(e2, rv.y, acc[2][1]);
        acc[2][2] = fmaf(e2, rv.z, acc[2][2]);
        acc[2][3] = fmaf(e2, rv.w, acc[2][3]);
        acc[3][0] = fmaf(e3, rv.x, acc[3][0]);
        acc[3][1] = fmaf(e3, rv.y, acc[3][1]);
        acc[3][2] = fmaf(e3, rv.z, acc[3][2]);
        acc[3][3] = fmaf(e3, rv.w, acc[3][3]);
    }

    // expsum: lanes 0..3 carry heads 0..3 (replicas identical across lane>>2)
    if (lane < 4) wred[w][lane] = lsum;

    // per-warp V accumulators to smem: head myh^j at dims lane*4..lane*4+3
#pragma unroll
    for (int j = 0; j < 4; j++) {
        float* wo_ = &wout[w][myh ^ j][lane * 4];
        wo_[0] = acc[j][0];
        wo_[1] = acc[j][1];
        wo_[2] = acc[j][2];
        wo_[3] = acc[j][3];
    }
    __syncthreads();

    if (tid < 4) {
        float v = wred[0][tid] + wred[1][tid] + wred[2][tid] + wred[3][tid];
        const int pbase = ((b * NKV + kv) * NSPLIT + c) * 4 + tid;
        g_ps[pbase] = v;
        g_pm[pbase] = 0.f;                  // common scale, no max needed
    }

    for (int i = tid; i < 4 * HDIM; i += 128) {
        const int h = i >> 7, d = i & 127;
        const float v = wout[0][h][d] + wout[1][h][d]
                      + wout[2][h][d] + wout[3][h][d];
        g_pa[(((size_t)(b * NKV + kv) * NSPLIT + c) * 4 + h) * HDIM + d] = v;
    }
}

// ---------------------------------------------------------------------------
__global__ __launch_bounds__(128) void combine_conv()
{
    const int hidx = blockIdx.x, b = blockIdx.y, d = threadIdx.x;
    const int kv = hidx >> 2, h = hidx & 3;
    const int pb = ((b * NKV + kv) * NSPLIT) * 4 + h;

    float m = -1e30f;
#pragma unroll
    for (int c = 0; c < NSPLIT; c++) m = fmaxf(m, g_pm[pb + c * 4]);
    float den = 0.f, wc[NSPLIT];
#pragma unroll
    for (int c = 0; c < NSPLIT; c++) {
        wc[c] = __expf(g_pm[pb + c * 4] - m);
        den   = fmaf(g_ps[pb + c * 4], wc[c], den);
    }
    const float inv = 1.f / den;

    float val = 0.f;
#pragma unroll
    for (int c = 0; c < NSPLIT; c++)
        val = fmaf(wc[c],
                   g_pa[(size_t)(((b * NKV + kv) * NSPLIT + c) * 4 + h) * HDIM + d],
                   val);
    const float r = val * inv;
    const __nv_bfloat16 hv = __float2bfloat16(r);
    const __nv_bfloat16 lv = __float2bfloat16(r - __bfloat162float(hv));
    g_ah[(size_t)b * HIDDEN + hidx * 128 + d] = hv;
    g_al[(size_t)b * HIDDEN + hidx * 128 + d] = lv;
}

__global__ __launch_bounds__(128) void reduce_out(float* __restrict__ out)
{
    const int tile = blockIdx.x, b = blockIdx.y, d = threadIdx.x;
    const size_t base = (size_t)tile * KS * 4096 + (size_t)b * 128 + d;
    float v = 0.f;
#pragma unroll
    for (int s = 0; s < KS; s++) v += g_part[base + (size_t)s * 4096];
    out[b * HIDDEN + tile * 128 + d] = v;
}

// ---------------------------------------------------------------------------
extern "C" void kernel_launch(void* const* d_in, const int* in_sizes, int n_in,
                              void* d_out, int out_size)
{
    const float* x        = (const float*)d_in[0];
    const float* position = (const float*)d_in[1];
    const float* k_cache  = (const float*)d_in[3];
    const float* v_cache  = (const float*)d_in[4];
    const float* wq       = (const float*)d_in[6];
    const float* wk       = (const float*)d_in[7];
    const float* wv       = (const float*)d_in[8];
    const float* wo       = (const float*)d_in[9];
    const float* qnw      = (const float*)d_in[10];
    const float* knw      = (const float*)d_in[11];
    float* out            = (float*)d_out;

    cudaFuncSetAttribute(gemm_qkv_mma, cudaFuncAttributeMaxDynamicSharedMemorySize, SMEM_MMA);
    cudaFuncSetAttribute(gemm_o_mma,   cudaFuncAttributeMaxDynamicSharedMemorySize, SMEM_MMA);

    prep_x<<<32, 256>>>(x);
    gemm_qkv_mma<<<dim3(24, KS), 256, SMEM_MMA>>>(wq, wk, wv);
    reduce_norm_rope<<<dim3(24, 32), 128>>>(position, qnw, knw);
    attn_part<<<dim3(NKV, 32, NSPLIT), 128>>>(k_cache, v_cache, position);
    combine_conv<<<dim3(16, 32), 128>>>();
    gemm_o_mma<<<dim3(16, KS), 256, SMEM_MMA>>>(wo);
    reduce_out<<<dim3(16, 32), 128>>>(out);
}